// round 3
// baseline (speedup 1.0000x reference)
#include <cuda_runtime.h>
#include <math.h>
#include <stdint.h>

#define BATCH 32
#define CH    128
#define NPIX  4096
#define HEADS 4
#define DH    32
#define HID   128
#define TP    128            // pixels per block tile
#define NT2   (NPIX / TP)    // 32
#define SCALE_Q 0.17677669529663687f  // 32^-0.5

#define PXP 136   // x/v/qsoft pixel-tile pitch  (8 mod 32 -> conflict-free B frags)
#define PWP 68    // weight stage pitch          (4 mod 32 -> conflict-free A frags)
#define PQP 132   // q/ek pitch                  (4 mod 32)
#define PMP 132   // M pitch in k_out

// -------- scratch (device globals; no allocation allowed) --------
__device__ float g_qsoft[(size_t)BATCH * HID * NPIX];              // softmaxed q * scale (tf32)
__device__ float g_Spart[(size_t)BATCH * NT2 * HEADS * DH * DH];   // per-tile context partials
__device__ float g_Zpart[(size_t)BATCH * NT2 * HID];               // per-tile denom partials
__device__ float g_M[BATCH * HID * HID];                           // w_out folded with context (tf32)

__device__ __forceinline__ float to_tf32(float x) {
    uint32_t u;
    asm("cvt.rna.tf32.f32 %0, %1;" : "=r"(u) : "f"(x));
    return __uint_as_float(u);
}

__device__ __forceinline__ void mma8(float* c,
                                     uint32_t a0, uint32_t a1, uint32_t a2, uint32_t a3,
                                     uint32_t b0, uint32_t b1) {
    asm volatile(
        "mma.sync.aligned.m16n8k8.row.col.f32.tf32.tf32.f32 "
        "{%0,%1,%2,%3},{%4,%5,%6,%7},{%8,%9},{%0,%1,%2,%3};"
        : "+f"(c[0]), "+f"(c[1]), "+f"(c[2]), "+f"(c[3])
        : "r"(a0), "r"(a1), "r"(a2), "r"(a3), "r"(b0), "r"(b1));
}

// ================= K2: fused norm + qkv GEMM + q softmax + partial context =================
// smem floats: sx[128*136] | sA[128*68] | sqk[128*132] | sg[128] | snorm[256] | szp[512]
#define K2_SMEM_FLOATS (CH*PXP + HID*PWP + HID*PQP + 128 + 256 + 512)
#define K2_SMEM_BYTES  (K2_SMEM_FLOATS * 4)

__global__ void __launch_bounds__(256) k_qkv(const float* __restrict__ x,
                                             const float* __restrict__ g,
                                             const float* __restrict__ wqkv) {
    extern __shared__ float sm[];
    float* sx    = sm;                 // [128 ch][PXP] x (tf32), later v tile
    float* sA    = sx + CH * PXP;      // [128 o][PWP] weight half-K stage
    float* sqk   = sA + HID * PWP;     // [128][PQP] q buffer, then exp(k)
    float* sg    = sqk + HID * PQP;    // [128]
    float* snorm = sg + 128;           // [256]
    float* szp   = snorm + 256;        // [4][128] Z partials per px-warp-group

    const int tid  = threadIdx.x;
    const int b    = blockIdx.y;
    const int tile = blockIdx.x;
    const int i0   = tile * TP;
    const int warp = tid >> 5, lane = tid & 31;
    const int ty   = lane >> 2, tx = lane & 3;
    const int wo   = warp >> 2;        // 0..1 : o rows wo*64..+63
    const int wp   = warp & 3;         // 0..3 : px wp*32..+31

    if (tid < 128) sg[tid] = g[tid];

    // ---- load raw x tile (coalesced float4) ----
    const float* xb = x + (size_t)b * CH * NPIX;
#pragma unroll
    for (int t = 0; t < 16; t++) {
        int e = tid + t * 256;
        int c = e >> 5, i4 = (e & 31) << 2;
        float4 v = *(const float4*)(xb + (size_t)c * NPIX + i0 + i4);
        *(float4*)(sx + c * PXP + i4) = v;
    }
    __syncthreads();

    // ---- per-pixel sum of squares ----
    {
        int px = tid & 127, grp = tid >> 7;
        float ss = 0.f;
#pragma unroll
        for (int j = 0; j < 64; j++) {
            float v = sx[(grp * 64 + j) * PXP + px];
            ss = fmaf(v, v, ss);
        }
        snorm[grp * 128 + px] = ss;
    }
    __syncthreads();
    if (tid < 128)
        snorm[tid] = 11.313708498984760f / fmaxf(sqrtf(snorm[tid] + snorm[128 + tid]), 1e-12f);
    __syncthreads();
    // ---- scale + tf32 convert in place ----
#pragma unroll
    for (int t = 0; t < 64; t++) {
        int e = tid + t * 256;
        int c = e >> 7, px = e & 127;
        sx[c * PXP + px] = to_tf32(sx[c * PXP + px] * sg[c] * snorm[px]);
    }

    float acc[4][4][4];
    for (int chunk = 0; chunk < 3; chunk++) {
#pragma unroll
        for (int mt = 0; mt < 4; mt++)
#pragma unroll
            for (int nt = 0; nt < 4; nt++) {
                acc[mt][nt][0] = 0.f; acc[mt][nt][1] = 0.f;
                acc[mt][nt][2] = 0.f; acc[mt][nt][3] = 0.f;
            }

        for (int kh = 0; kh < 2; kh++) {
            __syncthreads();
            // stage weights [o][k-half] as tf32
#pragma unroll
            for (int t = 0; t < 8; t++) {
                int e = tid + t * 256;
                int o = e >> 4, k4 = (e & 15) << 2;
                float4 wv = *(const float4*)(wqkv + (size_t)(chunk * HID + o) * CH + kh * 64 + k4);
                sA[o * PWP + k4]     = to_tf32(wv.x);
                sA[o * PWP + k4 + 1] = to_tf32(wv.y);
                sA[o * PWP + k4 + 2] = to_tf32(wv.z);
                sA[o * PWP + k4 + 3] = to_tf32(wv.w);
            }
            __syncthreads();
#pragma unroll
            for (int ks = 0; ks < 8; ks++) {
                int kk = ks * 8;
                int kg = kh * 64 + kk;
                uint32_t a[4][4];
#pragma unroll
                for (int mt = 0; mt < 4; mt++) {
                    const float* ap = sA + (wo * 64 + mt * 16 + ty) * PWP + kk + tx;
                    a[mt][0] = __float_as_uint(ap[0]);
                    a[mt][1] = __float_as_uint(ap[8 * PWP]);
                    a[mt][2] = __float_as_uint(ap[4]);
                    a[mt][3] = __float_as_uint(ap[8 * PWP + 4]);
                }
                uint32_t bb[4][2];
#pragma unroll
                for (int nt = 0; nt < 4; nt++) {
                    int px0 = wp * 32 + nt * 8 + ty;
                    bb[nt][0] = __float_as_uint(sx[(kg + tx) * PXP + px0]);
                    bb[nt][1] = __float_as_uint(sx[(kg + tx + 4) * PXP + px0]);
                }
#pragma unroll
                for (int mt = 0; mt < 4; mt++)
#pragma unroll
                    for (int nt = 0; nt < 4; nt++)
                        mma8(acc[mt][nt], a[mt][0], a[mt][1], a[mt][2], a[mt][3],
                             bb[nt][0], bb[nt][1]);
            }
        }

        if (chunk == 0) {
            // ---- q: park frags, softmax over d, write tf32 q ----
#pragma unroll
            for (int mt = 0; mt < 4; mt++)
#pragma unroll
                for (int nt = 0; nt < 4; nt++) {
                    int r = wo * 64 + mt * 16 + ty, c = wp * 32 + nt * 8 + 2 * tx;
                    *(float2*)(sqk + r * PQP + c)       = make_float2(acc[mt][nt][0], acc[mt][nt][1]);
                    *(float2*)(sqk + (r + 8) * PQP + c) = make_float2(acc[mt][nt][2], acc[mt][nt][3]);
                }
            __syncthreads();
#pragma unroll
            for (int rep = 0; rep < 2; rep++) {
                int h = rep * 2 + (tid >> 7), px = tid & 127;
                float* qr = sqk + (h * DH) * PQP + px;
                float m = -1e30f;
#pragma unroll
                for (int d = 0; d < DH; d++) m = fmaxf(m, qr[d * PQP]);
                float s = 0.f;
#pragma unroll
                for (int d = 0; d < DH; d++) {
                    float e = __expf(qr[d * PQP] - m);
                    qr[d * PQP] = e;
                    s += e;
                }
                float rs = SCALE_Q / s;
                float* qg = g_qsoft + ((size_t)b * HID + h * DH) * NPIX + i0 + px;
#pragma unroll
                for (int d = 0; d < DH; d++)
                    qg[(size_t)d * NPIX] = to_tf32(qr[d * PQP] * rs);
            }
        } else if (chunk == 1) {
            // ---- k: exp(k) frags (bounded, no max needed) + Z partials in regs ----
#pragma unroll
            for (int mt = 0; mt < 4; mt++) {
                float p0 = 0.f, p1 = 0.f;
                int r = wo * 64 + mt * 16 + ty;
#pragma unroll
                for (int nt = 0; nt < 4; nt++) {
                    float e0 = __expf(acc[mt][nt][0]);
                    float e1 = __expf(acc[mt][nt][1]);
                    float e2 = __expf(acc[mt][nt][2]);
                    float e3 = __expf(acc[mt][nt][3]);
                    int c = wp * 32 + nt * 8 + 2 * tx;
                    *(float2*)(sqk + r * PQP + c)       = make_float2(to_tf32(e0), to_tf32(e1));
                    *(float2*)(sqk + (r + 8) * PQP + c) = make_float2(to_tf32(e2), to_tf32(e3));
                    p0 += e0 + e1;
                    p1 += e2 + e3;
                }
                p0 += __shfl_xor_sync(0xFFFFFFFF, p0, 1);
                p0 += __shfl_xor_sync(0xFFFFFFFF, p0, 2);
                p1 += __shfl_xor_sync(0xFFFFFFFF, p1, 1);
                p1 += __shfl_xor_sync(0xFFFFFFFF, p1, 2);
                if (tx == 0) {
                    szp[wp * 128 + r]     = p0;
                    szp[wp * 128 + r + 8] = p1;
                }
            }
            __syncthreads();
            if (tid < 128) {
                float z = szp[tid] + szp[128 + tid] + szp[256 + tid] + szp[384 + tid];
                g_Zpart[(size_t)(b * NT2 + tile) * HID + tid] = z;
            }
        } else {
            // ---- v: overwrite sx with v (tf32), then context mma ----
            __syncthreads();   // all warps done reading sx
#pragma unroll
            for (int mt = 0; mt < 4; mt++)
#pragma unroll
                for (int nt = 0; nt < 4; nt++) {
                    int r = wo * 64 + mt * 16 + ty, c = wp * 32 + nt * 8 + 2 * tx;
                    *(float2*)(sx + r * PXP + c)       = make_float2(to_tf32(acc[mt][nt][0]), to_tf32(acc[mt][nt][1]));
                    *(float2*)(sx + (r + 8) * PXP + c) = make_float2(to_tf32(acc[mt][nt][2]), to_tf32(acc[mt][nt][3]));
                }
            __syncthreads();
            // S[h,d,e] = sum_px ek[h,d,px] * v[h,e,px]; warp -> (head, d-tile)
            int h = warp >> 1, dt = warp & 1;
            float cacc[4][4];
#pragma unroll
            for (int et = 0; et < 4; et++) {
                cacc[et][0] = 0.f; cacc[et][1] = 0.f; cacc[et][2] = 0.f; cacc[et][3] = 0.f;
            }
#pragma unroll
            for (int ksc = 0; ksc < 16; ksc++) {
                int ii = ksc * 8;
                const float* ap = sqk + (h * DH + dt * 16 + ty) * PQP + ii + tx;
                uint32_t a0 = __float_as_uint(ap[0]);
                uint32_t a1 = __float_as_uint(ap[8 * PQP]);
                uint32_t a2 = __float_as_uint(ap[4]);
                uint32_t a3 = __float_as_uint(ap[8 * PQP + 4]);
#pragma unroll
                for (int et = 0; et < 4; et++) {
                    const float* bp = sx + (h * DH + et * 8 + ty) * PXP + ii + tx;
                    uint32_t b0 = __float_as_uint(bp[0]);
                    uint32_t b1 = __float_as_uint(bp[4]);
                    mma8(cacc[et], a0, a1, a2, a3, b0, b1);
                }
            }
            float* sp = g_Spart + ((size_t)(b * NT2 + tile)) * (HEADS * DH * DH) + h * DH * DH;
#pragma unroll
            for (int et = 0; et < 4; et++) {
                int d = dt * 16 + ty, e = et * 8 + 2 * tx;
                *(float2*)(sp + d * DH + e)       = make_float2(cacc[et][0], cacc[et][1]);
                *(float2*)(sp + (d + 8) * DH + e) = make_float2(cacc[et][2], cacc[et][3]);
            }
        }
    }
}

// ================= K3: reduce partials, add mem_kv, fold context into w_out (tf32) =================
__global__ void __launch_bounds__(256) k_ctx(const float* __restrict__ mem_kv,
                                             const float* __restrict__ w_out) {
    __shared__ float sctx[HEADS * DH * DH];
    __shared__ float sZ[HID];
    int b = blockIdx.x, tid = threadIdx.x;

    if (tid < HID) {
        int h = tid >> 5, d = tid & 31;
        float z = 0.f;
        for (int t = 0; t < NT2; t++)
            z += g_Zpart[(size_t)(b * NT2 + t) * HID + tid];
        const float* mk = mem_kv + (h * DH + d) * 4;
        for (int j = 0; j < 4; j++) z += __expf(mk[j]);
        sZ[tid] = z;
    }
    __syncthreads();

    for (int idx = tid; idx < HEADS * DH * DH; idx += 256) {
        int h = idx >> 10, d = (idx >> 5) & 31, e = idx & 31;
        float s = 0.f;
#pragma unroll 4
        for (int t = 0; t < NT2; t++)
            s += g_Spart[(size_t)(b * NT2 + t) * (HEADS * DH * DH) + idx];
        const float* mk = mem_kv + (h * DH + d) * 4;
        const float* mv = mem_kv + (HEADS * DH + h * DH + e) * 4;
        for (int j = 0; j < 4; j++) s = fmaf(__expf(mk[j]), mv[j], s);
        sctx[idx] = s / sZ[h * DH + d];
    }
    __syncthreads();

    // M[co][h*32+d] = sum_e w_out[co][h*32+e] * ctx[h][d][e]   (stored tf32)
    for (int oidx = tid; oidx < HID * HID; oidx += 256) {
        int co = oidx >> 7, hd = oidx & 127;
        int h = hd >> 5, d = hd & 31;
        const float* wrow = w_out + co * HID + h * DH;
        const float* crow = sctx + h * DH * DH + d * DH;
        float m = 0.f;
#pragma unroll
        for (int e = 0; e < DH; e++) m = fmaf(wrow[e], crow[e], m);
        g_M[(size_t)(b * HID + co) * HID + hd] = to_tf32(m);
    }
}

// ================= K4: output GEMM: out = M @ qsoft + b_out =================
#define K4_SMEM_FLOATS (CH*PXP + HID*PMP)
#define K4_SMEM_BYTES  (K4_SMEM_FLOATS * 4)

__global__ void __launch_bounds__(256) k_out(const float* __restrict__ bout,
                                             float* __restrict__ out) {
    extern __shared__ float sm[];
    float* sB = sm;               // [128 k][PXP] qsoft tile; reused as output stage [128][PMP]
    float* sA = sB + CH * PXP;    // [128 o][PMP] M (tf32)
    __shared__ float sb[HID];

    const int tid  = threadIdx.x;
    const int b    = blockIdx.y;
    const int tile = blockIdx.x;
    const int i0   = tile * TP;
    const int warp = tid >> 5, lane = tid & 31;
    const int ty   = lane >> 2, tx = lane & 3;
    const int wo   = warp >> 2, wp = warp & 3;

    if (tid < HID) sb[tid] = bout[tid];

    const float* qb = g_qsoft + (size_t)b * HID * NPIX;
#pragma unroll
    for (int t = 0; t < 16; t++) {
        int e = tid + t * 256;
        int p = e >> 5, i4 = (e & 31) << 2;
        float4 v = *(const float4*)(qb + (size_t)p * NPIX + i0 + i4);
        *(float4*)(sB + p * PXP + i4) = v;
    }
    const float* Mb = g_M + (size_t)b * HID * HID;
#pragma unroll
    for (int t = 0; t < 16; t++) {
        int e = tid + t * 256;
        int o = e >> 5, k4 = (e & 31) << 2;
        float4 wv = *(const float4*)(Mb + o * HID + k4);
        *(float4*)(sA + o * PMP + k4) = wv;   // already tf32
    }
    __syncthreads();

    float acc[4][4][4];
#pragma unroll
    for (int mt = 0; mt < 4; mt++)
#pragma unroll
        for (int nt = 0; nt < 4; nt++) {
            acc[mt][nt][0] = 0.f; acc[mt][nt][1] = 0.f;
            acc[mt][nt][2] = 0.f; acc[mt][nt][3] = 0.f;
        }

#pragma unroll
    for (int ks = 0; ks < 16; ks++) {
        int kk = ks * 8;
        uint32_t a[4][4];
#pragma unroll
        for (int mt = 0; mt < 4; mt++) {
            const float* ap = sA + (wo * 64 + mt * 16 + ty) * PMP + kk + tx;
            a[mt][0] = __float_as_uint(ap[0]);
            a[mt][1] = __float_as_uint(ap[8 * PMP]);
            a[mt][2] = __float_as_uint(ap[4]);
            a[mt][3] = __float_as_uint(ap[8 * PMP + 4]);
        }
        uint32_t bb[4][2];
#pragma unroll
        for (int nt = 0; nt < 4; nt++) {
            int px0 = wp * 32 + nt * 8 + ty;
            bb[nt][0] = __float_as_uint(sB[(kk + tx) * PXP + px0]);
            bb[nt][1] = __float_as_uint(sB[(kk + tx + 4) * PXP + px0]);
        }
#pragma unroll
        for (int mt = 0; mt < 4; mt++)
#pragma unroll
            for (int nt = 0; nt < 4; nt++)
                mma8(acc[mt][nt], a[mt][0], a[mt][1], a[mt][2], a[mt][3],
                     bb[nt][0], bb[nt][1]);
    }
    __syncthreads();
    // stage output (+bias), then coalesced float4 copy out
#pragma unroll
    for (int mt = 0; mt < 4; mt++)
#pragma unroll
        for (int nt = 0; nt < 4; nt++) {
            int r = wo * 64 + mt * 16 + ty, c = wp * 32 + nt * 8 + 2 * tx;
            *(float2*)(sB + r * PMP + c)       = make_float2(acc[mt][nt][0] + sb[r], acc[mt][nt][1] + sb[r]);
            *(float2*)(sB + (r + 8) * PMP + c) = make_float2(acc[mt][nt][2] + sb[r + 8], acc[mt][nt][3] + sb[r + 8]);
        }
    __syncthreads();
    float* ob = out + (size_t)b * HID * NPIX + i0;
#pragma unroll
    for (int t = 0; t < 16; t++) {
        int e = tid + t * 256;
        int o = e >> 5, i4 = (e & 31) << 2;
        float4 v = *(const float4*)(sB + o * PMP + i4);
        *(float4*)(ob + (size_t)o * NPIX + i4) = v;
    }
}

// ================= launch =================
extern "C" void kernel_launch(void* const* d_in, const int* in_sizes, int n_in,
                              void* d_out, int out_size) {
    const float* x     = (const float*)d_in[0];
    const float* g     = (const float*)d_in[1];
    const float* wqkv  = (const float*)d_in[2];
    const float* memkv = (const float*)d_in[3];
    const float* wout  = (const float*)d_in[4];
    const float* bout  = (const float*)d_in[5];
    float* out = (float*)d_out;

    cudaFuncSetAttribute(k_qkv, cudaFuncAttributeMaxDynamicSharedMemorySize, K2_SMEM_BYTES);
    cudaFuncSetAttribute(k_out, cudaFuncAttributeMaxDynamicSharedMemorySize, K4_SMEM_BYTES);

    k_qkv<<<dim3(NT2, BATCH), 256, K2_SMEM_BYTES>>>(x, g, wqkv);
    k_ctx<<<BATCH, 256>>>(memkv, wout);
    k_out<<<dim3(NT2, BATCH), 256, K4_SMEM_BYTES>>>(bout, out);
}

// round 4
// speedup vs baseline: 1.4602x; 1.4602x over previous
#include <cuda_runtime.h>
#include <math.h>
#include <stdint.h>

#define BATCH 32
#define CH    128
#define NPIX  4096
#define HEADS 4
#define DH    32
#define HID   128
#define TP    128            // pixels per block tile
#define NT2   (NPIX / TP)    // 32
#define SCALE_Q 0.17677669529663687f  // 32^-0.5

#define PXP 136   // x/v/qsoft pixel pitch (8 mod 32 -> conflict-free B frags)
#define PWP 68    // weight stage pitch    (4 mod 32 -> conflict-free A frags)
#define PQP 132   // q/ek pitch            (4 mod 32)
#define PMP 132   // M pitch in k_out

// -------- scratch (device globals; no allocation allowed) --------
__device__ float g_qsoft[(size_t)BATCH * HID * NPIX];
__device__ float g_Spart[(size_t)BATCH * NT2 * HEADS * DH * DH];
__device__ float g_Zpart[(size_t)BATCH * NT2 * HID];
__device__ float g_M[BATCH * HID * HID];

__device__ __forceinline__ float to_tf32(float x) {
    uint32_t u;
    asm("cvt.rna.tf32.f32 %0, %1;" : "=r"(u) : "f"(x));
    return __uint_as_float(u);
}

__device__ __forceinline__ void mma8(float* c,
                                     uint32_t a0, uint32_t a1, uint32_t a2, uint32_t a3,
                                     uint32_t b0, uint32_t b1) {
    asm volatile(
        "mma.sync.aligned.m16n8k8.row.col.f32.tf32.tf32.f32 "
        "{%0,%1,%2,%3},{%4,%5,%6,%7},{%8,%9},{%0,%1,%2,%3};"
        : "+f"(c[0]), "+f"(c[1]), "+f"(c[2]), "+f"(c[3])
        : "r"(a0), "r"(a1), "r"(a2), "r"(a3), "r"(b0), "r"(b1));
}

// ================= K2: fused norm + qkv GEMM + q softmax + partial context =================
// smem floats: sx[128*136] | sA[128*68] | sqk[128*132] | sg[128] | snorm[512] | szp[512]
#define K2_SMEM_FLOATS (CH*PXP + HID*PWP + HID*PQP + 128 + 512 + 512)
#define K2_SMEM_BYTES  (K2_SMEM_FLOATS * 4)

__global__ void __launch_bounds__(512, 1) k_qkv(const float* __restrict__ x,
                                                const float* __restrict__ g,
                                                const float* __restrict__ wqkv) {
    extern __shared__ float sm[];
    float* sx    = sm;                 // [128 ch][PXP] x (tf32), later v tile
    float* sA    = sx + CH * PXP;      // [128 o][PWP] weight half-K stage
    float* sqk   = sA + HID * PWP;     // [128][PQP] q buffer, then exp(k)
    float* sg    = sqk + HID * PQP;    // [128]
    float* snorm = sg + 128;           // [512]
    float* szp   = snorm + 512;        // [4][128] Z partials per px-warp-group

    const int tid  = threadIdx.x;
    const int b    = blockIdx.y;
    const int tile = blockIdx.x;
    const int i0   = tile * TP;
    const int warp = tid >> 5, lane = tid & 31;
    const int ty   = lane >> 2, tx = lane & 3;
    const int wo   = warp >> 2;        // 0..3 : o rows wo*32..+31
    const int wp   = warp & 3;         // 0..3 : px wp*32..+31

    if (tid < 128) sg[tid] = g[tid];

    // ---- load raw x tile (coalesced float4) ----
    const float* xb = x + (size_t)b * CH * NPIX;
#pragma unroll
    for (int t = 0; t < 8; t++) {
        int e = tid + t * 512;
        int c = e >> 5, i4 = (e & 31) << 2;
        float4 v = *(const float4*)(xb + (size_t)c * NPIX + i0 + i4);
        *(float4*)(sx + c * PXP + i4) = v;
    }
    __syncthreads();

    // ---- per-pixel sum of squares ----
    {
        int px = tid & 127, grp = tid >> 7;   // 4 groups of 32 channels
        float ss = 0.f;
#pragma unroll
        for (int j = 0; j < 32; j++) {
            float v = sx[(grp * 32 + j) * PXP + px];
            ss = fmaf(v, v, ss);
        }
        snorm[grp * 128 + px] = ss;
    }
    __syncthreads();
    if (tid < 128) {
        float s = snorm[tid] + snorm[128 + tid] + snorm[256 + tid] + snorm[384 + tid];
        snorm[tid] = 11.313708498984760f / fmaxf(sqrtf(s), 1e-12f);
    }
    __syncthreads();
    // ---- scale + tf32 convert in place ----
#pragma unroll
    for (int t = 0; t < 32; t++) {
        int e = tid + t * 512;
        int c = e >> 7, px = e & 127;
        sx[c * PXP + px] = to_tf32(sx[c * PXP + px] * sg[c] * snorm[px]);
    }

    float acc[2][4][4];
    for (int chunk = 0; chunk < 3; chunk++) {
#pragma unroll
        for (int mt = 0; mt < 2; mt++)
#pragma unroll
            for (int nt = 0; nt < 4; nt++) {
                acc[mt][nt][0] = 0.f; acc[mt][nt][1] = 0.f;
                acc[mt][nt][2] = 0.f; acc[mt][nt][3] = 0.f;
            }

        for (int kh = 0; kh < 2; kh++) {
            __syncthreads();
            // stage weights [o][k-half] as tf32
#pragma unroll
            for (int t = 0; t < 4; t++) {
                int e = tid + t * 512;
                int o = e >> 4, k4 = (e & 15) << 2;
                float4 wv = *(const float4*)(wqkv + (size_t)(chunk * HID + o) * CH + kh * 64 + k4);
                sA[o * PWP + k4]     = to_tf32(wv.x);
                sA[o * PWP + k4 + 1] = to_tf32(wv.y);
                sA[o * PWP + k4 + 2] = to_tf32(wv.z);
                sA[o * PWP + k4 + 3] = to_tf32(wv.w);
            }
            __syncthreads();
#pragma unroll
            for (int ks = 0; ks < 8; ks++) {
                int kk = ks * 8;
                int kg = kh * 64 + kk;
                uint32_t a[2][4];
#pragma unroll
                for (int mt = 0; mt < 2; mt++) {
                    const float* ap = sA + (wo * 32 + mt * 16 + ty) * PWP + kk + tx;
                    a[mt][0] = __float_as_uint(ap[0]);
                    a[mt][1] = __float_as_uint(ap[8 * PWP]);
                    a[mt][2] = __float_as_uint(ap[4]);
                    a[mt][3] = __float_as_uint(ap[8 * PWP + 4]);
                }
                uint32_t bb[4][2];
#pragma unroll
                for (int nt = 0; nt < 4; nt++) {
                    int px0 = wp * 32 + nt * 8 + ty;
                    bb[nt][0] = __float_as_uint(sx[(kg + tx) * PXP + px0]);
                    bb[nt][1] = __float_as_uint(sx[(kg + tx + 4) * PXP + px0]);
                }
#pragma unroll
                for (int mt = 0; mt < 2; mt++)
#pragma unroll
                    for (int nt = 0; nt < 4; nt++)
                        mma8(acc[mt][nt], a[mt][0], a[mt][1], a[mt][2], a[mt][3],
                             bb[nt][0], bb[nt][1]);
            }
        }

        if (chunk == 0) {
            // ---- q: park frags, softmax over d, write tf32 q ----
#pragma unroll
            for (int mt = 0; mt < 2; mt++)
#pragma unroll
                for (int nt = 0; nt < 4; nt++) {
                    int r = wo * 32 + mt * 16 + ty, c = wp * 32 + nt * 8 + 2 * tx;
                    *(float2*)(sqk + r * PQP + c)       = make_float2(acc[mt][nt][0], acc[mt][nt][1]);
                    *(float2*)(sqk + (r + 8) * PQP + c) = make_float2(acc[mt][nt][2], acc[mt][nt][3]);
                }
            __syncthreads();
            {
                int h = tid >> 7, px = tid & 127;   // 4 heads * 128 px = 512
                float* qr = sqk + (h * DH) * PQP + px;
                float m = -1e30f;
#pragma unroll
                for (int d = 0; d < DH; d++) m = fmaxf(m, qr[d * PQP]);
                float s = 0.f;
#pragma unroll
                for (int d = 0; d < DH; d++) {
                    float e = __expf(qr[d * PQP] - m);
                    qr[d * PQP] = e;
                    s += e;
                }
                float rs = SCALE_Q / s;
                float* qg = g_qsoft + ((size_t)b * HID + h * DH) * NPIX + i0 + px;
#pragma unroll
                for (int d = 0; d < DH; d++)
                    qg[(size_t)d * NPIX] = to_tf32(qr[d * PQP] * rs);
            }
        } else if (chunk == 1) {
            // ---- k: exp(k) frags (bounded, no max) + Z partials via shuffles ----
#pragma unroll
            for (int mt = 0; mt < 2; mt++) {
                float p0 = 0.f, p1 = 0.f;
                int r = wo * 32 + mt * 16 + ty;
#pragma unroll
                for (int nt = 0; nt < 4; nt++) {
                    float e0 = __expf(acc[mt][nt][0]);
                    float e1 = __expf(acc[mt][nt][1]);
                    float e2 = __expf(acc[mt][nt][2]);
                    float e3 = __expf(acc[mt][nt][3]);
                    int c = wp * 32 + nt * 8 + 2 * tx;
                    *(float2*)(sqk + r * PQP + c)       = make_float2(to_tf32(e0), to_tf32(e1));
                    *(float2*)(sqk + (r + 8) * PQP + c) = make_float2(to_tf32(e2), to_tf32(e3));
                    p0 += e0 + e1;
                    p1 += e2 + e3;
                }
                p0 += __shfl_xor_sync(0xFFFFFFFF, p0, 1);
                p0 += __shfl_xor_sync(0xFFFFFFFF, p0, 2);
                p1 += __shfl_xor_sync(0xFFFFFFFF, p1, 1);
                p1 += __shfl_xor_sync(0xFFFFFFFF, p1, 2);
                if (tx == 0) {
                    szp[wp * 128 + r]     = p0;
                    szp[wp * 128 + r + 8] = p1;
                }
            }
            __syncthreads();
            if (tid < 128) {
                float z = szp[tid] + szp[128 + tid] + szp[256 + tid] + szp[384 + tid];
                g_Zpart[(size_t)(b * NT2 + tile) * HID + tid] = z;
            }
        } else {
            // ---- v: overwrite sx with v (tf32), then context mma ----
            __syncthreads();   // all warps done reading sx
#pragma unroll
            for (int mt = 0; mt < 2; mt++)
#pragma unroll
                for (int nt = 0; nt < 4; nt++) {
                    int r = wo * 32 + mt * 16 + ty, c = wp * 32 + nt * 8 + 2 * tx;
                    *(float2*)(sx + r * PXP + c)       = make_float2(to_tf32(acc[mt][nt][0]), to_tf32(acc[mt][nt][1]));
                    *(float2*)(sx + (r + 8) * PXP + c) = make_float2(to_tf32(acc[mt][nt][2]), to_tf32(acc[mt][nt][3]));
                }
            __syncthreads();
            // S[h,d,e] = sum_px ek[h,d,px] * v[h,e,px]
            // 16 warps: h = warp>>2, dt = (warp>>1)&1 (d-half), eh = warp&1 (e-half)
            int h = warp >> 2, dt = (warp >> 1) & 1, eh = warp & 1;
            float cacc[2][4];
#pragma unroll
            for (int et = 0; et < 2; et++) {
                cacc[et][0] = 0.f; cacc[et][1] = 0.f; cacc[et][2] = 0.f; cacc[et][3] = 0.f;
            }
#pragma unroll
            for (int ksc = 0; ksc < 16; ksc++) {
                int ii = ksc * 8;
                const float* ap = sqk + (h * DH + dt * 16 + ty) * PQP + ii + tx;
                uint32_t a0 = __float_as_uint(ap[0]);
                uint32_t a1 = __float_as_uint(ap[8 * PQP]);
                uint32_t a2 = __float_as_uint(ap[4]);
                uint32_t a3 = __float_as_uint(ap[8 * PQP + 4]);
#pragma unroll
                for (int et = 0; et < 2; et++) {
                    const float* bp = sx + (h * DH + eh * 16 + et * 8 + ty) * PXP + ii + tx;
                    uint32_t b0 = __float_as_uint(bp[0]);
                    uint32_t b1 = __float_as_uint(bp[4]);
                    mma8(cacc[et], a0, a1, a2, a3, b0, b1);
                }
            }
            float* sp = g_Spart + ((size_t)(b * NT2 + tile)) * (HEADS * DH * DH) + h * DH * DH;
#pragma unroll
            for (int et = 0; et < 2; et++) {
                int d = dt * 16 + ty, e = eh * 16 + et * 8 + 2 * tx;
                *(float2*)(sp + d * DH + e)       = make_float2(cacc[et][0], cacc[et][1]);
                *(float2*)(sp + (d + 8) * DH + e) = make_float2(cacc[et][2], cacc[et][3]);
            }
        }
    }
}

// ================= K3: reduce partials per (b, head), fold context into w_out =================
__global__ void __launch_bounds__(256) k_ctx(const float* __restrict__ mem_kv,
                                             const float* __restrict__ w_out) {
    __shared__ float sctx[DH * DH];
    __shared__ float sZ[DH];
    int b = blockIdx.x, h = blockIdx.y, tid = threadIdx.x;

    if (tid < DH) {
        int d = tid;
        float z = 0.f;
#pragma unroll 4
        for (int t = 0; t < NT2; t++)
            z += g_Zpart[(size_t)(b * NT2 + t) * HID + h * DH + d];
        const float* mk = mem_kv + (h * DH + d) * 4;
        for (int j = 0; j < 4; j++) z += __expf(mk[j]);
        sZ[d] = z;
    }
    __syncthreads();

    for (int idx = tid; idx < DH * DH; idx += 256) {
        int d = idx >> 5, e = idx & 31;
        float s = 0.f;
#pragma unroll 4
        for (int t = 0; t < NT2; t++)
            s += g_Spart[(size_t)(b * NT2 + t) * (HEADS * DH * DH) + h * DH * DH + idx];
        const float* mk = mem_kv + (h * DH + d) * 4;
        const float* mv = mem_kv + (HEADS * DH + h * DH + e) * 4;
        for (int j = 0; j < 4; j++) s = fmaf(__expf(mk[j]), mv[j], s);
        sctx[idx] = s / sZ[d];
    }
    __syncthreads();

    // M[co][h*32+d] = sum_e w_out[co][h*32+e] * ctx[d][e]   (stored tf32)
    for (int oidx = tid; oidx < HID * DH; oidx += 256) {
        int co = oidx >> 5, d = oidx & 31;
        const float* wrow = w_out + co * HID + h * DH;
        const float* crow = sctx + d * DH;
        float m = 0.f;
#pragma unroll
        for (int e = 0; e < DH; e++) m = fmaf(wrow[e], crow[e], m);
        g_M[(size_t)(b * HID + co) * HID + h * DH + d] = to_tf32(m);
    }
}

// ================= K4: output GEMM: out = M @ qsoft + b_out =================
#define K4_SMEM_FLOATS (CH*PXP + HID*PMP)
#define K4_SMEM_BYTES  (K4_SMEM_FLOATS * 4)

__global__ void __launch_bounds__(512, 1) k_out(const float* __restrict__ bout,
                                                float* __restrict__ out) {
    extern __shared__ float sm[];
    float* sB = sm;               // [128 k][PXP] qsoft tile; reused as output stage
    float* sA = sB + CH * PXP;    // [128 o][PMP] M (tf32)
    __shared__ float sb[HID];

    const int tid  = threadIdx.x;
    const int b    = blockIdx.y;
    const int tile = blockIdx.x;
    const int i0   = tile * TP;
    const int warp = tid >> 5, lane = tid & 31;
    const int ty   = lane >> 2, tx = lane & 3;
    const int wo   = warp >> 2, wp = warp & 3;

    if (tid < HID) sb[tid] = bout[tid];

    const float* qb = g_qsoft + (size_t)b * HID * NPIX;
#pragma unroll
    for (int t = 0; t < 8; t++) {
        int e = tid + t * 512;
        int p = e >> 5, i4 = (e & 31) << 2;
        float4 v = *(const float4*)(qb + (size_t)p * NPIX + i0 + i4);
        *(float4*)(sB + p * PXP + i4) = v;
    }
    const float* Mb = g_M + (size_t)b * HID * HID;
#pragma unroll
    for (int t = 0; t < 8; t++) {
        int e = tid + t * 512;
        int o = e >> 5, k4 = (e & 31) << 2;
        float4 wv = *(const float4*)(Mb + o * HID + k4);
        *(float4*)(sA + o * PMP + k4) = wv;   // already tf32
    }
    __syncthreads();

    float acc[2][4][4];
#pragma unroll
    for (int mt = 0; mt < 2; mt++)
#pragma unroll
        for (int nt = 0; nt < 4; nt++) {
            acc[mt][nt][0] = 0.f; acc[mt][nt][1] = 0.f;
            acc[mt][nt][2] = 0.f; acc[mt][nt][3] = 0.f;
        }

#pragma unroll
    for (int ks = 0; ks < 16; ks++) {
        int kk = ks * 8;
        uint32_t a[2][4];
#pragma unroll
        for (int mt = 0; mt < 2; mt++) {
            const float* ap = sA + (wo * 32 + mt * 16 + ty) * PMP + kk + tx;
            a[mt][0] = __float_as_uint(ap[0]);
            a[mt][1] = __float_as_uint(ap[8 * PMP]);
            a[mt][2] = __float_as_uint(ap[4]);
            a[mt][3] = __float_as_uint(ap[8 * PMP + 4]);
        }
        uint32_t bb[4][2];
#pragma unroll
        for (int nt = 0; nt < 4; nt++) {
            int px0 = wp * 32 + nt * 8 + ty;
            bb[nt][0] = __float_as_uint(sB[(kk + tx) * PXP + px0]);
            bb[nt][1] = __float_as_uint(sB[(kk + tx + 4) * PXP + px0]);
        }
#pragma unroll
        for (int mt = 0; mt < 2; mt++)
#pragma unroll
            for (int nt = 0; nt < 4; nt++)
                mma8(acc[mt][nt], a[mt][0], a[mt][1], a[mt][2], a[mt][3],
                     bb[nt][0], bb[nt][1]);
    }
    __syncthreads();
    // stage output (+bias), then coalesced float4 copy out
#pragma unroll
    for (int mt = 0; mt < 2; mt++)
#pragma unroll
        for (int nt = 0; nt < 4; nt++) {
            int r = wo * 32 + mt * 16 + ty, c = wp * 32 + nt * 8 + 2 * tx;
            *(float2*)(sB + r * PXP + c)       = make_float2(acc[mt][nt][0] + sb[r], acc[mt][nt][1] + sb[r]);
            *(float2*)(sB + (r + 8) * PXP + c) = make_float2(acc[mt][nt][2] + sb[r + 8], acc[mt][nt][3] + sb[r + 8]);
        }
    __syncthreads();
    float* ob = out + (size_t)b * HID * NPIX + i0;
#pragma unroll
    for (int t = 0; t < 8; t++) {
        int e = tid + t * 512;
        int o = e >> 5, i4 = (e & 31) << 2;
        float4 v = *(const float4*)(sB + o * PXP + i4);
        *(float4*)(ob + (size_t)o * NPIX + i4) = v;
    }
}

// ================= launch =================
extern "C" void kernel_launch(void* const* d_in, const int* in_sizes, int n_in,
                              void* d_out, int out_size) {
    const float* x     = (const float*)d_in[0];
    const float* g     = (const float*)d_in[1];
    const float* wqkv  = (const float*)d_in[2];
    const float* memkv = (const float*)d_in[3];
    const float* wout  = (const float*)d_in[4];
    const float* bout  = (const float*)d_in[5];
    float* out = (float*)d_out;

    cudaFuncSetAttribute(k_qkv, cudaFuncAttributeMaxDynamicSharedMemorySize, K2_SMEM_BYTES);
    cudaFuncSetAttribute(k_out, cudaFuncAttributeMaxDynamicSharedMemorySize, K4_SMEM_BYTES);

    k_qkv<<<dim3(NT2, BATCH), 512, K2_SMEM_BYTES>>>(x, g, wqkv);
    k_ctx<<<dim3(BATCH, HEADS), 256>>>(memkv, wout);
    k_out<<<dim3(NT2, BATCH), 512, K4_SMEM_BYTES>>>(bout, out);
}

// round 5
// speedup vs baseline: 1.5177x; 1.0393x over previous
#include <cuda_runtime.h>
#include <math.h>
#include <stdint.h>

#define BATCH 32
#define CH    128
#define NPIX  4096
#define HEADS 4
#define DH    32
#define HID   128
#define TP    128            // k_qkv pixels per block tile
#define NT2   (NPIX / TP)    // 32
#define TPO   64             // k_out pixels per block tile
#define NTO   (NPIX / TPO)   // 64
#define SCALE_Q 0.17677669529663687f  // 32^-0.5

#define PXP 136   // x/v pixel pitch (8 mod 32 -> conflict-free B frags)
#define PAP 132   // weight pitch    (4 mod 32 -> conflict-free A frags)
#define PQP 132   // q/ek pitch      (4 mod 32)
#define PXO 72    // k_out q-tile pitch (8 mod 32)

// -------- scratch (device globals; no allocation allowed) --------
__device__ float g_qsoft[(size_t)BATCH * HID * NPIX];
__device__ float g_Spart[(size_t)BATCH * NT2 * HEADS * DH * DH];
__device__ float g_Zpart[(size_t)BATCH * NT2 * HID];
__device__ float g_M[BATCH * HID * HID];

__device__ __forceinline__ float to_tf32(float x) {
    uint32_t u;
    asm("cvt.rna.tf32.f32 %0, %1;" : "=r"(u) : "f"(x));
    return __uint_as_float(u);
}

__device__ __forceinline__ void mma8(float* c,
                                     uint32_t a0, uint32_t a1, uint32_t a2, uint32_t a3,
                                     uint32_t b0, uint32_t b1) {
    asm volatile(
        "mma.sync.aligned.m16n8k8.row.col.f32.tf32.tf32.f32 "
        "{%0,%1,%2,%3},{%4,%5,%6,%7},{%8,%9},{%0,%1,%2,%3};"
        : "+f"(c[0]), "+f"(c[1]), "+f"(c[2]), "+f"(c[3])
        : "r"(a0), "r"(a1), "r"(a2), "r"(a3), "r"(b0), "r"(b1));
}

// ================= K2: fused norm + qkv GEMM + q softmax + partial context =================
// smem floats: sx[128*136] | sA[128*132] | sqk[128*132] | sg[128] | snorm[512] | szp[512]
#define K2_SMEM_FLOATS (CH*PXP + HID*PAP + HID*PQP + 128 + 512 + 512)
#define K2_SMEM_BYTES  (K2_SMEM_FLOATS * 4)

__global__ void __launch_bounds__(512, 1) k_qkv(const float* __restrict__ x,
                                                const float* __restrict__ g,
                                                const float* __restrict__ wqkv) {
    extern __shared__ float sm[];
    float* sx    = sm;                 // [128 ch][PXP] x (tf32), later v tile
    float* sA    = sx + CH * PXP;      // [128 o][PAP] full-chunk weights (tf32)
    float* sqk   = sA + HID * PAP;     // [128][PQP] q buffer, then exp(k)
    float* sg    = sqk + HID * PQP;    // [128]
    float* snorm = sg + 128;           // [512]: sumsq partials, then softmax rs per (h,px)
    float* szp   = snorm + 512;        // [4][128] Z partials

    const int tid  = threadIdx.x;
    const int b    = blockIdx.y;
    const int tile = blockIdx.x;
    const int i0   = tile * TP;
    const int warp = tid >> 5, lane = tid & 31;
    const int ty   = lane >> 2, tx = lane & 3;
    const int wo   = warp >> 2;        // 0..3 : o rows wo*32..+31
    const int wp   = warp & 3;         // 0..3 : px wp*32..+31

    if (tid < 128) sg[tid] = g[tid];

    // ---- P0: load raw x tile  ||  stage chunk-0 weights ----
    const float* xb = x + (size_t)b * CH * NPIX;
#pragma unroll
    for (int t = 0; t < 8; t++) {
        int e = tid + t * 512;
        int c = e >> 5, i4 = (e & 31) << 2;
        float4 v = *(const float4*)(xb + (size_t)c * NPIX + i0 + i4);
        *(float4*)(sx + c * PXP + i4) = v;
    }
#pragma unroll
    for (int t = 0; t < 8; t++) {
        int e = tid + t * 512;
        int o = e >> 5, k4 = (e & 31) << 2;
        float4 wv = *(const float4*)(wqkv + (size_t)o * CH + k4);  // chunk 0
        sA[o * PAP + k4]     = to_tf32(wv.x);
        sA[o * PAP + k4 + 1] = to_tf32(wv.y);
        sA[o * PAP + k4 + 2] = to_tf32(wv.z);
        sA[o * PAP + k4 + 3] = to_tf32(wv.w);
    }
    __syncthreads();

    // ---- P1: per-pixel sum-of-squares partials ----
    {
        int px = tid & 127, grp = tid >> 7;
        float ss = 0.f;
#pragma unroll
        for (int j = 0; j < 32; j++) {
            float v = sx[(grp * 32 + j) * PXP + px];
            ss = fmaf(v, v, ss);
        }
        snorm[grp * 128 + px] = ss;
    }
    __syncthreads();
    // ---- P2: norm scale ----
    if (tid < 128) {
        float s = snorm[tid] + snorm[128 + tid] + snorm[256 + tid] + snorm[384 + tid];
        snorm[tid] = 11.313708498984760f / fmaxf(sqrtf(s), 1e-12f);
    }
    __syncthreads();
    // ---- P3: scale + tf32 convert sx in place ----
#pragma unroll
    for (int t = 0; t < 32; t++) {
        int e = tid + t * 512;
        int c = e >> 7, px = e & 127;
        sx[c * PXP + px] = to_tf32(sx[c * PXP + px] * sg[c] * snorm[px]);
    }
    __syncthreads();

    float acc[2][4][4];
#define ZERO_ACC() \
    _Pragma("unroll") for (int mt = 0; mt < 2; mt++) \
    _Pragma("unroll") for (int nt = 0; nt < 4; nt++) { \
        acc[mt][nt][0] = 0.f; acc[mt][nt][1] = 0.f; acc[mt][nt][2] = 0.f; acc[mt][nt][3] = 0.f; }

#define MMA_CHUNK() \
    _Pragma("unroll") \
    for (int ks = 0; ks < 16; ks++) { \
        int kk = ks * 8; \
        uint32_t a[2][4]; \
        _Pragma("unroll") \
        for (int mt = 0; mt < 2; mt++) { \
            const float* ap = sA + (wo * 32 + mt * 16 + ty) * PAP + kk + tx; \
            a[mt][0] = __float_as_uint(ap[0]); \
            a[mt][1] = __float_as_uint(ap[8 * PAP]); \
            a[mt][2] = __float_as_uint(ap[4]); \
            a[mt][3] = __float_as_uint(ap[8 * PAP + 4]); \
        } \
        uint32_t bb[4][2]; \
        _Pragma("unroll") \
        for (int nt = 0; nt < 4; nt++) { \
            int px0 = wp * 32 + nt * 8 + ty; \
            bb[nt][0] = __float_as_uint(sx[(kk + tx) * PXP + px0]); \
            bb[nt][1] = __float_as_uint(sx[(kk + tx + 4) * PXP + px0]); \
        } \
        _Pragma("unroll") \
        for (int mt = 0; mt < 2; mt++) \
        _Pragma("unroll") \
        for (int nt = 0; nt < 4; nt++) \
            mma8(acc[mt][nt], a[mt][0], a[mt][1], a[mt][2], a[mt][3], bb[nt][0], bb[nt][1]); \
    }

#define STAGE_W(CHUNK) \
    _Pragma("unroll") \
    for (int t = 0; t < 8; t++) { \
        int e = tid + t * 512; \
        int o = e >> 5, k4 = (e & 31) << 2; \
        float4 wv = *(const float4*)(wqkv + (size_t)((CHUNK) * HID + o) * CH + k4); \
        sA[o * PAP + k4]     = to_tf32(wv.x); \
        sA[o * PAP + k4 + 1] = to_tf32(wv.y); \
        sA[o * PAP + k4 + 2] = to_tf32(wv.z); \
        sA[o * PAP + k4 + 3] = to_tf32(wv.w); \
    }

    // ---- P4: chunk 0 (q) mma + park into sqk ----
    ZERO_ACC();
    MMA_CHUNK();
#pragma unroll
    for (int mt = 0; mt < 2; mt++)
#pragma unroll
        for (int nt = 0; nt < 4; nt++) {
            int r = wo * 32 + mt * 16 + ty, c = wp * 32 + nt * 8 + 2 * tx;
            *(float2*)(sqk + r * PQP + c)       = make_float2(acc[mt][nt][0], acc[mt][nt][1]);
            *(float2*)(sqk + (r + 8) * PQP + c) = make_float2(acc[mt][nt][2], acc[mt][nt][3]);
        }
    __syncthreads();

    // ---- P5: softmax over d (rs -> snorm, e back into sqk)  ||  stage chunk-1 weights ----
    {
        int h = tid >> 7, px = tid & 127;
        float* qr = sqk + (h * DH) * PQP + px;
        float m = -1e30f;
#pragma unroll
        for (int d = 0; d < DH; d++) m = fmaxf(m, qr[d * PQP]);
        float s = 0.f;
#pragma unroll
        for (int d = 0; d < DH; d++) {
            float e = __expf(qr[d * PQP] - m);
            qr[d * PQP] = e;
            s += e;
        }
        snorm[h * 128 + px] = SCALE_Q / s;
    }
    STAGE_W(1);
    __syncthreads();

    // ---- P6: q write-out (coalesced float4)  ||  chunk 1 (k) mma ----
    {
        float* qg = g_qsoft + (size_t)b * HID * NPIX + i0;
#pragma unroll
        for (int t = 0; t < 8; t++) {
            int e = tid + t * 512;
            int row = e >> 5, px4 = (e & 31) << 2;
            int h = row >> 5;
            float4 ev = *(const float4*)(sqk + row * PQP + px4);
            float4 rs = *(const float4*)(snorm + h * 128 + px4);
            float4 ov;
            ov.x = to_tf32(ev.x * rs.x);
            ov.y = to_tf32(ev.y * rs.y);
            ov.z = to_tf32(ev.z * rs.z);
            ov.w = to_tf32(ev.w * rs.w);
            *(float4*)(qg + (size_t)row * NPIX + px4) = ov;
        }
    }
    ZERO_ACC();
    MMA_CHUNK();
    __syncthreads();

    // ---- P7: exp(k) park into sqk + Z shuffle partials  ||  stage chunk-2 weights ----
#pragma unroll
    for (int mt = 0; mt < 2; mt++) {
        float p0 = 0.f, p1 = 0.f;
        int r = wo * 32 + mt * 16 + ty;
#pragma unroll
        for (int nt = 0; nt < 4; nt++) {
            float e0 = __expf(acc[mt][nt][0]);
            float e1 = __expf(acc[mt][nt][1]);
            float e2 = __expf(acc[mt][nt][2]);
            float e3 = __expf(acc[mt][nt][3]);
            int c = wp * 32 + nt * 8 + 2 * tx;
            *(float2*)(sqk + r * PQP + c)       = make_float2(to_tf32(e0), to_tf32(e1));
            *(float2*)(sqk + (r + 8) * PQP + c) = make_float2(to_tf32(e2), to_tf32(e3));
            p0 += e0 + e1;
            p1 += e2 + e3;
        }
        p0 += __shfl_xor_sync(0xFFFFFFFF, p0, 1);
        p0 += __shfl_xor_sync(0xFFFFFFFF, p0, 2);
        p1 += __shfl_xor_sync(0xFFFFFFFF, p1, 1);
        p1 += __shfl_xor_sync(0xFFFFFFFF, p1, 2);
        if (tx == 0) {
            szp[wp * 128 + r]     = p0;
            szp[wp * 128 + r + 8] = p1;
        }
    }
    STAGE_W(2);
    __syncthreads();

    // ---- P8: Z reduce+write  ||  chunk 2 (v) mma ----
    if (tid < 128) {
        float z = szp[tid] + szp[128 + tid] + szp[256 + tid] + szp[384 + tid];
        g_Zpart[(size_t)(b * NT2 + tile) * HID + tid] = z;
    }
    ZERO_ACC();
    MMA_CHUNK();
    __syncthreads();

    // ---- P9: v park into sx (tf32) ----
#pragma unroll
    for (int mt = 0; mt < 2; mt++)
#pragma unroll
        for (int nt = 0; nt < 4; nt++) {
            int r = wo * 32 + mt * 16 + ty, c = wp * 32 + nt * 8 + 2 * tx;
            *(float2*)(sx + r * PXP + c)       = make_float2(to_tf32(acc[mt][nt][0]), to_tf32(acc[mt][nt][1]));
            *(float2*)(sx + (r + 8) * PXP + c) = make_float2(to_tf32(acc[mt][nt][2]), to_tf32(acc[mt][nt][3]));
        }
    __syncthreads();

    // ---- P10: context mma  S[h,d,e] = sum_px ek[h,d,px] * v[h,e,px] ----
    {
        int h = warp >> 2, dt = (warp >> 1) & 1, eh = warp & 1;
        float cacc[2][4];
#pragma unroll
        for (int et = 0; et < 2; et++) {
            cacc[et][0] = 0.f; cacc[et][1] = 0.f; cacc[et][2] = 0.f; cacc[et][3] = 0.f;
        }
#pragma unroll
        for (int ksc = 0; ksc < 16; ksc++) {
            int ii = ksc * 8;
            const float* ap = sqk + (h * DH + dt * 16 + ty) * PQP + ii + tx;
            uint32_t a0 = __float_as_uint(ap[0]);
            uint32_t a1 = __float_as_uint(ap[8 * PQP]);
            uint32_t a2 = __float_as_uint(ap[4]);
            uint32_t a3 = __float_as_uint(ap[8 * PQP + 4]);
#pragma unroll
            for (int et = 0; et < 2; et++) {
                const float* bp = sx + (h * DH + eh * 16 + et * 8 + ty) * PXP + ii + tx;
                uint32_t b0 = __float_as_uint(bp[0]);
                uint32_t b1 = __float_as_uint(bp[4]);
                mma8(cacc[et], a0, a1, a2, a3, b0, b1);
            }
        }
        float* sp = g_Spart + ((size_t)(b * NT2 + tile)) * (HEADS * DH * DH) + h * DH * DH;
#pragma unroll
        for (int et = 0; et < 2; et++) {
            int d = dt * 16 + ty, e = eh * 16 + et * 8 + 2 * tx;
            *(float2*)(sp + d * DH + e)       = make_float2(cacc[et][0], cacc[et][1]);
            *(float2*)(sp + (d + 8) * DH + e) = make_float2(cacc[et][2], cacc[et][3]);
        }
    }
#undef ZERO_ACC
#undef MMA_CHUNK
#undef STAGE_W
}

// ================= K3: reduce partials per (b, head), fold context into w_out =================
__global__ void __launch_bounds__(256) k_ctx(const float* __restrict__ mem_kv,
                                             const float* __restrict__ w_out) {
    __shared__ float sctx[DH * DH];
    __shared__ float sZ[DH];
    int b = blockIdx.x, h = blockIdx.y, tid = threadIdx.x;

    if (tid < DH) {
        int d = tid;
        float z = 0.f;
#pragma unroll 4
        for (int t = 0; t < NT2; t++)
            z += g_Zpart[(size_t)(b * NT2 + t) * HID + h * DH + d];
        const float* mk = mem_kv + (h * DH + d) * 4;
        for (int j = 0; j < 4; j++) z += __expf(mk[j]);
        sZ[d] = z;
    }
    __syncthreads();

    for (int idx = tid; idx < DH * DH; idx += 256) {
        int d = idx >> 5, e = idx & 31;
        float s = 0.f;
#pragma unroll 4
        for (int t = 0; t < NT2; t++)
            s += g_Spart[(size_t)(b * NT2 + t) * (HEADS * DH * DH) + h * DH * DH + idx];
        const float* mk = mem_kv + (h * DH + d) * 4;
        const float* mv = mem_kv + (HEADS * DH + h * DH + e) * 4;
        for (int j = 0; j < 4; j++) s = fmaf(__expf(mk[j]), mv[j], s);
        sctx[idx] = s / sZ[d];
    }
    __syncthreads();

    for (int oidx = tid; oidx < HID * DH; oidx += 256) {
        int co = oidx >> 5, d = oidx & 31;
        const float* wrow = w_out + co * HID + h * DH;
        const float* crow = sctx + d * DH;
        float m = 0.f;
#pragma unroll
        for (int e = 0; e < DH; e++) m = fmaf(wrow[e], crow[e], m);
        g_M[(size_t)(b * HID + co) * HID + h * DH + d] = to_tf32(m);
    }
}

// ================= K4: output GEMM: out = M @ qsoft + b_out  (2 blocks/SM) =================
#define K4_SMEM_FLOATS (CH*PXO + HID*PAP)
#define K4_SMEM_BYTES  (K4_SMEM_FLOATS * 4)

__global__ void __launch_bounds__(256, 2) k_out(const float* __restrict__ bout,
                                                float* __restrict__ out) {
    extern __shared__ float sm[];
    float* sB = sm;               // [128 k][PXO] q tile; reused as output stage
    float* sA = sB + CH * PXO;    // [128 o][PAP] M (tf32)
    __shared__ float sb[HID];

    const int tid  = threadIdx.x;
    const int b    = blockIdx.y;
    const int tile = blockIdx.x;
    const int i0   = tile * TPO;
    const int warp = tid >> 5, lane = tid & 31;
    const int ty   = lane >> 2, tx = lane & 3;
    const int wo   = warp >> 1;        // 0..3 : o rows wo*32
    const int wp   = warp & 1;         // 0..1 : px wp*32

    if (tid < HID) sb[tid] = bout[tid];

    const float* qb = g_qsoft + (size_t)b * HID * NPIX;
#pragma unroll
    for (int t = 0; t < 8; t++) {
        int e = tid + t * 256;
        int p = e >> 4, i4 = (e & 15) << 2;
        float4 v = *(const float4*)(qb + (size_t)p * NPIX + i0 + i4);
        *(float4*)(sB + p * PXO + i4) = v;
    }
    const float* Mb = g_M + (size_t)b * HID * HID;
#pragma unroll
    for (int t = 0; t < 16; t++) {
        int e = tid + t * 256;
        int o = e >> 5, k4 = (e & 31) << 2;
        float4 wv = *(const float4*)(Mb + o * HID + k4);
        *(float4*)(sA + o * PAP + k4) = wv;   // already tf32
    }
    __syncthreads();

    float acc[2][4][4];
#pragma unroll
    for (int mt = 0; mt < 2; mt++)
#pragma unroll
        for (int nt = 0; nt < 4; nt++) {
            acc[mt][nt][0] = 0.f; acc[mt][nt][1] = 0.f;
            acc[mt][nt][2] = 0.f; acc[mt][nt][3] = 0.f;
        }

#pragma unroll
    for (int ks = 0; ks < 16; ks++) {
        int kk = ks * 8;
        uint32_t a[2][4];
#pragma unroll
        for (int mt = 0; mt < 2; mt++) {
            const float* ap = sA + (wo * 32 + mt * 16 + ty) * PAP + kk + tx;
            a[mt][0] = __float_as_uint(ap[0]);
            a[mt][1] = __float_as_uint(ap[8 * PAP]);
            a[mt][2] = __float_as_uint(ap[4]);
            a[mt][3] = __float_as_uint(ap[8 * PAP + 4]);
        }
        uint32_t bb[4][2];
#pragma unroll
        for (int nt = 0; nt < 4; nt++) {
            int px0 = wp * 32 + nt * 8 + ty;
            bb[nt][0] = __float_as_uint(sB[(kk + tx) * PXO + px0]);
            bb[nt][1] = __float_as_uint(sB[(kk + tx + 4) * PXO + px0]);
        }
#pragma unroll
        for (int mt = 0; mt < 2; mt++)
#pragma unroll
            for (int nt = 0; nt < 4; nt++)
                mma8(acc[mt][nt], a[mt][0], a[mt][1], a[mt][2], a[mt][3],
                     bb[nt][0], bb[nt][1]);
    }
    __syncthreads();
    // stage output (+bias), then coalesced float4 copy out
#pragma unroll
    for (int mt = 0; mt < 2; mt++)
#pragma unroll
        for (int nt = 0; nt < 4; nt++) {
            int r = wo * 32 + mt * 16 + ty, c = wp * 32 + nt * 8 + 2 * tx;
            *(float2*)(sB + r * PXO + c)       = make_float2(acc[mt][nt][0] + sb[r], acc[mt][nt][1] + sb[r]);
            *(float2*)(sB + (r + 8) * PXO + c) = make_float2(acc[mt][nt][2] + sb[r + 8], acc[mt][nt][3] + sb[r + 8]);
        }
    __syncthreads();
    float* ob = out + (size_t)b * HID * NPIX + i0;
#pragma unroll
    for (int t = 0; t < 8; t++) {
        int e = tid + t * 256;
        int o = e >> 4, i4 = (e & 15) << 2;
        float4 v = *(const float4*)(sB + o * PXO + i4);
        *(float4*)(ob + (size_t)o * NPIX + i4) = v;
    }
}

// ================= launch =================
extern "C" void kernel_launch(void* const* d_in, const int* in_sizes, int n_in,
                              void* d_out, int out_size) {
    const float* x     = (const float*)d_in[0];
    const float* g     = (const float*)d_in[1];
    const float* wqkv  = (const float*)d_in[2];
    const float* memkv = (const float*)d_in[3];
    const float* wout  = (const float*)d_in[4];
    const float* bout  = (const float*)d_in[5];
    float* out = (float*)d_out;

    cudaFuncSetAttribute(k_qkv, cudaFuncAttributeMaxDynamicSharedMemorySize, K2_SMEM_BYTES);
    cudaFuncSetAttribute(k_out, cudaFuncAttributeMaxDynamicSharedMemorySize, K4_SMEM_BYTES);

    k_qkv<<<dim3(NT2, BATCH), 512, K2_SMEM_BYTES>>>(x, g, wqkv);
    k_ctx<<<dim3(BATCH, HEADS), 256>>>(memkv, wout);
    k_out<<<dim3(NTO, BATCH), 256, K4_SMEM_BYTES>>>(bout, out);
}

// round 6
// speedup vs baseline: 1.5275x; 1.0065x over previous
#include <cuda_runtime.h>
#include <math.h>
#include <stdint.h>

#define BATCH 32
#define CH    128
#define NPIX  4096
#define HEADS 4
#define DH    32
#define HID   128
#define TP    128            // k_qkv pixels per block tile
#define NT2   (NPIX / TP)    // 32
#define TPO   64             // k_out pixels per block tile
#define NTO   (NPIX / TPO)   // 64
#define SCALE_Q 0.17677669529663687f  // 32^-0.5

#define PXP 136   // x/v pixel pitch (8 mod 32 -> conflict-free B frags)
#define PAP 132   // weight pitch    (4 mod 32 -> conflict-free A frags)
#define PQP 132   // q/ek pitch      (4 mod 32)
#define PXO 72    // k_out q-tile pitch (8 mod 32)

// -------- scratch (device globals; no allocation allowed) --------
__device__ float g_qsoft[(size_t)BATCH * HID * NPIX];
__device__ float g_Spart[(size_t)BATCH * NT2 * HEADS * DH * DH];
__device__ float g_Zpart[(size_t)BATCH * NT2 * HID];
__device__ float g_M[BATCH * HID * HID];

__device__ __forceinline__ float to_tf32(float x) {
    uint32_t u;
    asm("cvt.rna.tf32.f32 %0, %1;" : "=r"(u) : "f"(x));
    return __uint_as_float(u);
}

__device__ __forceinline__ void mma8(float* c,
                                     uint32_t a0, uint32_t a1, uint32_t a2, uint32_t a3,
                                     uint32_t b0, uint32_t b1) {
    asm volatile(
        "mma.sync.aligned.m16n8k8.row.col.f32.tf32.tf32.f32 "
        "{%0,%1,%2,%3},{%4,%5,%6,%7},{%8,%9},{%0,%1,%2,%3};"
        : "+f"(c[0]), "+f"(c[1]), "+f"(c[2]), "+f"(c[3])
        : "r"(a0), "r"(a1), "r"(a2), "r"(a3), "r"(b0), "r"(b1));
}

// ================= K2: fused norm + qkv GEMM + q softmax + partial context =================
// smem floats: sx[128*136] | sA[128*132] | sqk[128*132] | sg[128] | snorm[512] | szp[512]
#define K2_SMEM_FLOATS (CH*PXP + HID*PAP + HID*PQP + 128 + 512 + 512)
#define K2_SMEM_BYTES  (K2_SMEM_FLOATS * 4)

__global__ void __launch_bounds__(512, 1) k_qkv(const float* __restrict__ x,
                                                const float* __restrict__ g,
                                                const float* __restrict__ wqkv) {
    extern __shared__ float sm[];
    float* sx    = sm;                 // [128 ch][PXP] x (tf32), later v tile
    float* sA    = sx + CH * PXP;      // [128 o][PAP] full-chunk weights (tf32)
    float* sqk   = sA + HID * PAP;     // [128][PQP] q buffer, then exp(k)
    float* sg    = sqk + HID * PQP;    // [128]
    float* snorm = sg + 128;           // [512]: sumsq partials, then softmax rs per (h,px)
    float* szp   = snorm + 512;        // [4][128] Z partials

    const int tid  = threadIdx.x;
    const int b    = blockIdx.y;
    const int tile = blockIdx.x;
    const int i0   = tile * TP;
    const int warp = tid >> 5, lane = tid & 31;
    const int ty   = lane >> 2, tx = lane & 3;
    const int wo   = warp >> 2;        // 0..3 : o rows wo*32..+31
    const int wp   = warp & 3;         // 0..3 : px wp*32..+31

    if (tid < 128) sg[tid] = g[tid];

    // ---- P0: load raw x tile  ||  stage chunk-0 weights ----
    const float* xb = x + (size_t)b * CH * NPIX;
#pragma unroll
    for (int t = 0; t < 8; t++) {
        int e = tid + t * 512;
        int c = e >> 5, i4 = (e & 31) << 2;
        float4 v = *(const float4*)(xb + (size_t)c * NPIX + i0 + i4);
        *(float4*)(sx + c * PXP + i4) = v;
    }
#pragma unroll
    for (int t = 0; t < 8; t++) {
        int e = tid + t * 512;
        int o = e >> 5, k4 = (e & 31) << 2;
        float4 wv = *(const float4*)(wqkv + (size_t)o * CH + k4);  // chunk 0
        sA[o * PAP + k4]     = to_tf32(wv.x);
        sA[o * PAP + k4 + 1] = to_tf32(wv.y);
        sA[o * PAP + k4 + 2] = to_tf32(wv.z);
        sA[o * PAP + k4 + 3] = to_tf32(wv.w);
    }
    __syncthreads();

    // ---- P1: per-pixel sum-of-squares partials ----
    {
        int px = tid & 127, grp = tid >> 7;
        float ss = 0.f;
#pragma unroll
        for (int j = 0; j < 32; j++) {
            float v = sx[(grp * 32 + j) * PXP + px];
            ss = fmaf(v, v, ss);
        }
        snorm[grp * 128 + px] = ss;
    }
    __syncthreads();
    // ---- P2: norm scale ----
    if (tid < 128) {
        float s = snorm[tid] + snorm[128 + tid] + snorm[256 + tid] + snorm[384 + tid];
        snorm[tid] = 11.313708498984760f / fmaxf(sqrtf(s), 1e-12f);
    }
    __syncthreads();
    // ---- P3: scale + tf32 convert sx in place ----
#pragma unroll
    for (int t = 0; t < 32; t++) {
        int e = tid + t * 512;
        int c = e >> 7, px = e & 127;
        sx[c * PXP + px] = to_tf32(sx[c * PXP + px] * sg[c] * snorm[px]);
    }
    __syncthreads();

    float acc[2][4][4];
#define ZERO_ACC() \
    _Pragma("unroll") for (int mt = 0; mt < 2; mt++) \
    _Pragma("unroll") for (int nt = 0; nt < 4; nt++) { \
        acc[mt][nt][0] = 0.f; acc[mt][nt][1] = 0.f; acc[mt][nt][2] = 0.f; acc[mt][nt][3] = 0.f; }

#define MMA_CHUNK() \
    _Pragma("unroll") \
    for (int ks = 0; ks < 16; ks++) { \
        int kk = ks * 8; \
        uint32_t a[2][4]; \
        _Pragma("unroll") \
        for (int mt = 0; mt < 2; mt++) { \
            const float* ap = sA + (wo * 32 + mt * 16 + ty) * PAP + kk + tx; \
            a[mt][0] = __float_as_uint(ap[0]); \
            a[mt][1] = __float_as_uint(ap[8 * PAP]); \
            a[mt][2] = __float_as_uint(ap[4]); \
            a[mt][3] = __float_as_uint(ap[8 * PAP + 4]); \
        } \
        uint32_t bb[4][2]; \
        _Pragma("unroll") \
        for (int nt = 0; nt < 4; nt++) { \
            int px0 = wp * 32 + nt * 8 + ty; \
            bb[nt][0] = __float_as_uint(sx[(kk + tx) * PXP + px0]); \
            bb[nt][1] = __float_as_uint(sx[(kk + tx + 4) * PXP + px0]); \
        } \
        _Pragma("unroll") \
        for (int mt = 0; mt < 2; mt++) \
        _Pragma("unroll") \
        for (int nt = 0; nt < 4; nt++) \
            mma8(acc[mt][nt], a[mt][0], a[mt][1], a[mt][2], a[mt][3], bb[nt][0], bb[nt][1]); \
    }

#define STAGE_W(CHUNK) \
    _Pragma("unroll") \
    for (int t = 0; t < 8; t++) { \
        int e = tid + t * 512; \
        int o = e >> 5, k4 = (e & 31) << 2; \
        float4 wv = *(const float4*)(wqkv + (size_t)((CHUNK) * HID + o) * CH + k4); \
        sA[o * PAP + k4]     = to_tf32(wv.x); \
        sA[o * PAP + k4 + 1] = to_tf32(wv.y); \
        sA[o * PAP + k4 + 2] = to_tf32(wv.z); \
        sA[o * PAP + k4 + 3] = to_tf32(wv.w); \
    }

    // ---- P4: chunk 0 (q) mma + park into sqk ----
    ZERO_ACC();
    MMA_CHUNK();
#pragma unroll
    for (int mt = 0; mt < 2; mt++)
#pragma unroll
        for (int nt = 0; nt < 4; nt++) {
            int r = wo * 32 + mt * 16 + ty, c = wp * 32 + nt * 8 + 2 * tx;
            *(float2*)(sqk + r * PQP + c)       = make_float2(acc[mt][nt][0], acc[mt][nt][1]);
            *(float2*)(sqk + (r + 8) * PQP + c) = make_float2(acc[mt][nt][2], acc[mt][nt][3]);
        }
    __syncthreads();

    // ---- P5: softmax over d (rs -> snorm, e back into sqk)  ||  stage chunk-1 weights ----
    {
        int h = tid >> 7, px = tid & 127;
        float* qr = sqk + (h * DH) * PQP + px;
        float m = -1e30f;
#pragma unroll
        for (int d = 0; d < DH; d++) m = fmaxf(m, qr[d * PQP]);
        float s = 0.f;
#pragma unroll
        for (int d = 0; d < DH; d++) {
            float e = __expf(qr[d * PQP] - m);
            qr[d * PQP] = e;
            s += e;
        }
        snorm[h * 128 + px] = SCALE_Q / s;
    }
    STAGE_W(1);
    __syncthreads();

    // ---- P6: q write-out (coalesced float4)  ||  chunk 1 (k) mma ----
    {
        float* qg = g_qsoft + (size_t)b * HID * NPIX + i0;
#pragma unroll
        for (int t = 0; t < 8; t++) {
            int e = tid + t * 512;
            int row = e >> 5, px4 = (e & 31) << 2;
            int h = row >> 5;
            float4 ev = *(const float4*)(sqk + row * PQP + px4);
            float4 rs = *(const float4*)(snorm + h * 128 + px4);
            float4 ov;
            ov.x = to_tf32(ev.x * rs.x);
            ov.y = to_tf32(ev.y * rs.y);
            ov.z = to_tf32(ev.z * rs.z);
            ov.w = to_tf32(ev.w * rs.w);
            *(float4*)(qg + (size_t)row * NPIX + px4) = ov;
        }
    }
    ZERO_ACC();
    MMA_CHUNK();
    __syncthreads();

    // ---- P7: exp(k) park into sqk + Z shuffle partials  ||  stage chunk-2 weights ----
#pragma unroll
    for (int mt = 0; mt < 2; mt++) {
        float p0 = 0.f, p1 = 0.f;
        int r = wo * 32 + mt * 16 + ty;
#pragma unroll
        for (int nt = 0; nt < 4; nt++) {
            float e0 = __expf(acc[mt][nt][0]);
            float e1 = __expf(acc[mt][nt][1]);
            float e2 = __expf(acc[mt][nt][2]);
            float e3 = __expf(acc[mt][nt][3]);
            int c = wp * 32 + nt * 8 + 2 * tx;
            *(float2*)(sqk + r * PQP + c)       = make_float2(to_tf32(e0), to_tf32(e1));
            *(float2*)(sqk + (r + 8) * PQP + c) = make_float2(to_tf32(e2), to_tf32(e3));
            p0 += e0 + e1;
            p1 += e2 + e3;
        }
        p0 += __shfl_xor_sync(0xFFFFFFFF, p0, 1);
        p0 += __shfl_xor_sync(0xFFFFFFFF, p0, 2);
        p1 += __shfl_xor_sync(0xFFFFFFFF, p1, 1);
        p1 += __shfl_xor_sync(0xFFFFFFFF, p1, 2);
        if (tx == 0) {
            szp[wp * 128 + r]     = p0;
            szp[wp * 128 + r + 8] = p1;
        }
    }
    STAGE_W(2);
    __syncthreads();

    // ---- P8: Z reduce+write  ||  chunk 2 (v) mma ----
    if (tid < 128) {
        float z = szp[tid] + szp[128 + tid] + szp[256 + tid] + szp[384 + tid];
        g_Zpart[(size_t)(b * NT2 + tile) * HID + tid] = z;
    }
    ZERO_ACC();
    MMA_CHUNK();
    __syncthreads();

    // ---- P9: v park into sx (tf32) ----
#pragma unroll
    for (int mt = 0; mt < 2; mt++)
#pragma unroll
        for (int nt = 0; nt < 4; nt++) {
            int r = wo * 32 + mt * 16 + ty, c = wp * 32 + nt * 8 + 2 * tx;
            *(float2*)(sx + r * PXP + c)       = make_float2(to_tf32(acc[mt][nt][0]), to_tf32(acc[mt][nt][1]));
            *(float2*)(sx + (r + 8) * PXP + c) = make_float2(to_tf32(acc[mt][nt][2]), to_tf32(acc[mt][nt][3]));
        }
    __syncthreads();

    // ---- P10: context mma  S[h,d,e] = sum_px ek[h,d,px] * v[h,e,px] ----
    {
        int h = warp >> 2, dt = (warp >> 1) & 1, eh = warp & 1;
        float cacc[2][4];
#pragma unroll
        for (int et = 0; et < 2; et++) {
            cacc[et][0] = 0.f; cacc[et][1] = 0.f; cacc[et][2] = 0.f; cacc[et][3] = 0.f;
        }
#pragma unroll
        for (int ksc = 0; ksc < 16; ksc++) {
            int ii = ksc * 8;
            const float* ap = sqk + (h * DH + dt * 16 + ty) * PQP + ii + tx;
            uint32_t a0 = __float_as_uint(ap[0]);
            uint32_t a1 = __float_as_uint(ap[8 * PQP]);
            uint32_t a2 = __float_as_uint(ap[4]);
            uint32_t a3 = __float_as_uint(ap[8 * PQP + 4]);
#pragma unroll
            for (int et = 0; et < 2; et++) {
                const float* bp = sx + (h * DH + eh * 16 + et * 8 + ty) * PXP + ii + tx;
                uint32_t b0 = __float_as_uint(bp[0]);
                uint32_t b1 = __float_as_uint(bp[4]);
                mma8(cacc[et], a0, a1, a2, a3, b0, b1);
            }
        }
        float* sp = g_Spart + ((size_t)(b * NT2 + tile)) * (HEADS * DH * DH) + h * DH * DH;
#pragma unroll
        for (int et = 0; et < 2; et++) {
            int d = dt * 16 + ty, e = eh * 16 + et * 8 + 2 * tx;
            *(float2*)(sp + d * DH + e)       = make_float2(cacc[et][0], cacc[et][1]);
            *(float2*)(sp + (d + 8) * DH + e) = make_float2(cacc[et][2], cacc[et][3]);
        }
    }
#undef ZERO_ACC
#undef MMA_CHUNK
#undef STAGE_W
}

// ================= K3: reduce partials per (b, head), fold context into w_out =================
__global__ void __launch_bounds__(256) k_ctx(const float* __restrict__ mem_kv,
                                             const float* __restrict__ w_out) {
    __shared__ float sctx[DH * DH];
    __shared__ float sZ[DH];
    int b = blockIdx.x, h = blockIdx.y, tid = threadIdx.x;

    if (tid < DH) {
        int d = tid;
        float z = 0.f;
#pragma unroll 4
        for (int t = 0; t < NT2; t++)
            z += g_Zpart[(size_t)(b * NT2 + t) * HID + h * DH + d];
        const float* mk = mem_kv + (h * DH + d) * 4;
        for (int j = 0; j < 4; j++) z += __expf(mk[j]);
        sZ[d] = z;
    }
    __syncthreads();

    for (int idx = tid; idx < DH * DH; idx += 256) {
        int d = idx >> 5, e = idx & 31;
        float s = 0.f;
#pragma unroll 4
        for (int t = 0; t < NT2; t++)
            s += g_Spart[(size_t)(b * NT2 + t) * (HEADS * DH * DH) + h * DH * DH + idx];
        const float* mk = mem_kv + (h * DH + d) * 4;
        const float* mv = mem_kv + (HEADS * DH + h * DH + e) * 4;
        for (int j = 0; j < 4; j++) s = fmaf(__expf(mk[j]), mv[j], s);
        sctx[idx] = s / sZ[d];
    }
    __syncthreads();

    for (int oidx = tid; oidx < HID * DH; oidx += 256) {
        int co = oidx >> 5, d = oidx & 31;
        const float* wrow = w_out + co * HID + h * DH;
        const float* crow = sctx + d * DH;
        float m = 0.f;
#pragma unroll
        for (int e = 0; e < DH; e++) m = fmaf(wrow[e], crow[e], m);
        g_M[(size_t)(b * HID + co) * HID + h * DH + d] = to_tf32(m);
    }
}

// ================= K4: output GEMM: out = M @ qsoft + b_out  (2 blocks/SM) =================
#define K4_SMEM_FLOATS (CH*PXO + HID*PAP)
#define K4_SMEM_BYTES  (K4_SMEM_FLOATS * 4)

__global__ void __launch_bounds__(256, 2) k_out(const float* __restrict__ bout,
                                                float* __restrict__ out) {
    extern __shared__ float sm[];
    float* sB = sm;               // [128 k][PXO] q tile; reused as output stage
    float* sA = sB + CH * PXO;    // [128 o][PAP] M (tf32)
    __shared__ float sb[HID];

    const int tid  = threadIdx.x;
    const int b    = blockIdx.y;
    const int tile = blockIdx.x;
    const int i0   = tile * TPO;
    const int warp = tid >> 5, lane = tid & 31;
    const int ty   = lane >> 2, tx = lane & 3;
    const int wo   = warp >> 1;        // 0..3 : o rows wo*32
    const int wp   = warp & 1;         // 0..1 : px wp*32

    if (tid < HID) sb[tid] = bout[tid];

    const float* qb = g_qsoft + (size_t)b * HID * NPIX;
#pragma unroll
    for (int t = 0; t < 8; t++) {
        int e = tid + t * 256;
        int p = e >> 4, i4 = (e & 15) << 2;
        float4 v = *(const float4*)(qb + (size_t)p * NPIX + i0 + i4);
        *(float4*)(sB + p * PXO + i4) = v;
    }
    const float* Mb = g_M + (size_t)b * HID * HID;
#pragma unroll
    for (int t = 0; t < 16; t++) {
        int e = tid + t * 256;
        int o = e >> 5, k4 = (e & 31) << 2;
        float4 wv = *(const float4*)(Mb + o * HID + k4);
        *(float4*)(sA + o * PAP + k4) = wv;   // already tf32
    }
    __syncthreads();

    float acc[2][4][4];
#pragma unroll
    for (int mt = 0; mt < 2; mt++)
#pragma unroll
        for (int nt = 0; nt < 4; nt++) {
            acc[mt][nt][0] = 0.f; acc[mt][nt][1] = 0.f;
            acc[mt][nt][2] = 0.f; acc[mt][nt][3] = 0.f;
        }

#pragma unroll
    for (int ks = 0; ks < 16; ks++) {
        int kk = ks * 8;
        uint32_t a[2][4];
#pragma unroll
        for (int mt = 0; mt < 2; mt++) {
            const float* ap = sA + (wo * 32 + mt * 16 + ty) * PAP + kk + tx;
            a[mt][0] = __float_as_uint(ap[0]);
            a[mt][1] = __float_as_uint(ap[8 * PAP]);
            a[mt][2] = __float_as_uint(ap[4]);
            a[mt][3] = __float_as_uint(ap[8 * PAP + 4]);
        }
        uint32_t bb[4][2];
#pragma unroll
        for (int nt = 0; nt < 4; nt++) {
            int px0 = wp * 32 + nt * 8 + ty;
            bb[nt][0] = __float_as_uint(sB[(kk + tx) * PXO + px0]);
            bb[nt][1] = __float_as_uint(sB[(kk + tx + 4) * PXO + px0]);
        }
#pragma unroll
        for (int mt = 0; mt < 2; mt++)
#pragma unroll
            for (int nt = 0; nt < 4; nt++)
                mma8(acc[mt][nt], a[mt][0], a[mt][1], a[mt][2], a[mt][3],
                     bb[nt][0], bb[nt][1]);
    }
    __syncthreads();
    // stage output (+bias), then coalesced float4 copy out
#pragma unroll
    for (int mt = 0; mt < 2; mt++)
#pragma unroll
        for (int nt = 0; nt < 4; nt++) {
            int r = wo * 32 + mt * 16 + ty, c = wp * 32 + nt * 8 + 2 * tx;
            *(float2*)(sB + r * PXO + c)       = make_float2(acc[mt][nt][0] + sb[r], acc[mt][nt][1] + sb[r]);
            *(float2*)(sB + (r + 8) * PXO + c) = make_float2(acc[mt][nt][2] + sb[r + 8], acc[mt][nt][3] + sb[r + 8]);
        }
    __syncthreads();
    float* ob = out + (size_t)b * HID * NPIX + i0;
#pragma unroll
    for (int t = 0; t < 8; t++) {
        int e = tid + t * 256;
        int o = e >> 4, i4 = (e & 15) << 2;
        float4 v = *(const float4*)(sB + o * PXO + i4);
        *(float4*)(ob + (size_t)o * NPIX + i4) = v;
    }
}

// ================= launch =================
extern "C" void kernel_launch(void* const* d_in, const int* in_sizes, int n_in,
                              void* d_out, int out_size) {
    const float* x     = (const float*)d_in[0];
    const float* g     = (const float*)d_in[1];
    const float* wqkv  = (const float*)d_in[2];
    const float* memkv = (const float*)d_in[3];
    const float* wout  = (const float*)d_in[4];
    const float* bout  = (const float*)d_in[5];
    float* out = (float*)d_out;

    cudaFuncSetAttribute(k_qkv, cudaFuncAttributeMaxDynamicSharedMemorySize, K2_SMEM_BYTES);
    cudaFuncSetAttribute(k_out, cudaFuncAttributeMaxDynamicSharedMemorySize, K4_SMEM_BYTES);

    k_qkv<<<dim3(NT2, BATCH), 512, K2_SMEM_BYTES>>>(x, g, wqkv);
    k_ctx<<<dim3(BATCH, HEADS), 256>>>(memkv, wout);
    k_out<<<dim3(NTO, BATCH), 256, K4_SMEM_BYTES>>>(bout, out);
}

// round 9
// speedup vs baseline: 1.6281x; 1.0659x over previous
#include <cuda_runtime.h>
#include <math.h>
#include <stdint.h>

#define BATCH 32
#define CH    128
#define NPIX  4096
#define HEADS 4
#define DH    32
#define HID   128
#define TP    128            // k_qkv pixels per block tile
#define NT2   (NPIX / TP)    // 32
#define TPO   64             // k_out pixels per block tile
#define NTO   (NPIX / TPO)   // 64
#define SCALE_Q 0.17677669529663687f  // 32^-0.5

#define PXP 136   // x/v pixel pitch (8 mod 32 -> conflict-free B frags)
#define PQP 132   // ek pitch        (4 mod 32)
#define PXO 72    // k_out q-tile pitch (8 mod 32)

// -------- scratch (device globals; no allocation allowed) --------
__device__ float g_qsoft[(size_t)BATCH * HID * NPIX];
__device__ float g_Spart[(size_t)BATCH * NT2 * HEADS * DH * DH];
__device__ float g_Zpart[(size_t)BATCH * NT2 * HID];
__device__ float g_wperm[3 * HID * CH];        // frag-major tf32 qkv weights
__device__ float g_Mperm[BATCH * HID * HID];   // frag-major tf32 folded output weights

__device__ __forceinline__ float to_tf32(float x) {
    uint32_t u;
    asm("cvt.rna.tf32.f32 %0, %1;" : "=r"(u) : "f"(x));
    return __uint_as_float(u);
}

__device__ __forceinline__ void mma8(float* c,
                                     uint32_t a0, uint32_t a1, uint32_t a2, uint32_t a3,
                                     uint32_t b0, uint32_t b1) {
    asm volatile(
        "mma.sync.aligned.m16n8k8.row.col.f32.tf32.tf32.f32 "
        "{%0,%1,%2,%3},{%4,%5,%6,%7},{%8,%9},{%0,%1,%2,%3};"
        : "+f"(c[0]), "+f"(c[1]), "+f"(c[2]), "+f"(c[3])
        : "r"(a0), "r"(a1), "r"(a2), "r"(a3), "r"(b0), "r"(b1));
}

// frag-major position for A value at (row r16 in 0..15 within otile, col c8 in 0..7 within ktile)
__device__ __forceinline__ int frag_pos(int ktile, int otile, int r, int c) {
    int lane = (r & 7) * 4 + (c & 3);
    int slot = ((c >> 2) << 1) + (r >> 3);
    return ((ktile * 8 + otile) * 32 + lane) * 4 + slot;
}

// ================= K0: pre-permute qkv weights to fragment-major tf32 =================
__global__ void k_prep(const float* __restrict__ wqkv) {
    int idx = blockIdx.x * 256 + threadIdx.x;       // 0 .. 3*16384-1
    int cc  = idx >> 14;
    int rem = idx & 16383;
    int o = rem >> 7, k = rem & 127;
    float w = to_tf32(wqkv[idx]);                   // idx == (cc*128+o)*128 + k
    g_wperm[cc * 16384 + frag_pos(k >> 3, o >> 4, o & 15, k & 7)] = w;
}

// ================= K2: fused norm + qkv GEMM + q softmax + partial context =================
// smem floats: sx[128*136] | sA[16384] | sek[128*132] | sg[128] | snorm[512] | szp[512]
#define K2_SMEM_FLOATS (CH*PXP + 16384 + HID*PQP + 128 + 512 + 512)
#define K2_SMEM_BYTES  (K2_SMEM_FLOATS * 4)

__global__ void __launch_bounds__(512, 1) k_qkv(const float* __restrict__ x,
                                                const float* __restrict__ g) {
    extern __shared__ float sm[];
    float* sx    = sm;                 // [128 ch][PXP] x (tf32), later v tile
    float* sA    = sx + CH * PXP;      // [16384] frag-major chunk weights
    float* sek   = sA + 16384;         // [128][PQP] exp(k)
    float* sg    = sek + HID * PQP;    // [128]
    float* snorm = sg + 128;           // [512]
    float* szp   = snorm + 512;        // [4][128]

    const int tid  = threadIdx.x;
    const int b    = blockIdx.y;
    const int tile = blockIdx.x;
    const int i0   = tile * TP;
    const int warp = tid >> 5, lane = tid & 31;
    const int ty   = lane >> 2, tx = lane & 3;
    const int wo   = warp >> 2;        // 0..3 : o rows wo*32..+31 (= head for q)
    const int wp   = warp & 3;         // 0..3 : px wp*32..+31

    if (tid < 128) sg[tid] = g[tid];

    // ---- P0: load raw x tile || stage chunk-0 weights (plain copy) ----
    const float* xb = x + (size_t)b * CH * NPIX;
#pragma unroll
    for (int t = 0; t < 8; t++) {
        int e = tid + t * 512;
        int c = e >> 5, i4 = (e & 31) << 2;
        float4 v = *(const float4*)(xb + (size_t)c * NPIX + i0 + i4);
        *(float4*)(sx + c * PXP + i4) = v;
    }
#pragma unroll
    for (int t = 0; t < 8; t++) {
        int i4 = (tid + t * 512) << 2;
        *(float4*)(sA + i4) = *(const float4*)(g_wperm + i4);
    }
    __syncthreads();

    // ---- P1: per-pixel sum-of-squares partials ----
    {
        int px = tid & 127, grp = tid >> 7;
        float ss = 0.f;
#pragma unroll
        for (int j = 0; j < 32; j++) {
            float v = sx[(grp * 32 + j) * PXP + px];
            ss = fmaf(v, v, ss);
        }
        snorm[grp * 128 + px] = ss;
    }
    __syncthreads();
    if (tid < 128) {
        float s = snorm[tid] + snorm[128 + tid] + snorm[256 + tid] + snorm[384 + tid];
        snorm[tid] = 11.313708498984760f / fmaxf(sqrtf(s), 1e-12f);
    }
    __syncthreads();
    // ---- P3: scale + tf32 convert sx in place ----
#pragma unroll
    for (int t = 0; t < 32; t++) {
        int e = tid + t * 512;
        int c = e >> 7, px = e & 127;
        sx[c * PXP + px] = to_tf32(sx[c * PXP + px] * sg[c] * snorm[px]);
    }
    __syncthreads();

    float acc[2][4][4];
#define ZERO_ACC() \
    _Pragma("unroll") for (int mt = 0; mt < 2; mt++) \
    _Pragma("unroll") for (int nt = 0; nt < 4; nt++) { \
        acc[mt][nt][0] = 0.f; acc[mt][nt][1] = 0.f; acc[mt][nt][2] = 0.f; acc[mt][nt][3] = 0.f; }

#define MMA_CHUNK() \
    _Pragma("unroll") \
    for (int ks = 0; ks < 16; ks++) { \
        int kk = ks * 8; \
        float4 af0 = *(const float4*)(sA + ((ks * 8 + 2 * wo + 0) * 32 + lane) * 4); \
        float4 af1 = *(const float4*)(sA + ((ks * 8 + 2 * wo + 1) * 32 + lane) * 4); \
        uint32_t bb[4][2]; \
        _Pragma("unroll") \
        for (int nt = 0; nt < 4; nt++) { \
            int px0 = wp * 32 + nt * 8 + ty; \
            bb[nt][0] = __float_as_uint(sx[(kk + tx) * PXP + px0]); \
            bb[nt][1] = __float_as_uint(sx[(kk + tx + 4) * PXP + px0]); \
        } \
        _Pragma("unroll") \
        for (int nt = 0; nt < 4; nt++) { \
            mma8(acc[0][nt], __float_as_uint(af0.x), __float_as_uint(af0.y), \
                 __float_as_uint(af0.z), __float_as_uint(af0.w), bb[nt][0], bb[nt][1]); \
            mma8(acc[1][nt], __float_as_uint(af1.x), __float_as_uint(af1.y), \
                 __float_as_uint(af1.z), __float_as_uint(af1.w), bb[nt][0], bb[nt][1]); \
        } \
    }

#define STAGE_W(CHUNK) \
    _Pragma("unroll") \
    for (int t = 0; t < 8; t++) { \
        int i4 = (tid + t * 512) << 2; \
        *(float4*)(sA + i4) = *(const float4*)(g_wperm + (CHUNK) * 16384 + i4); \
    }

    // ---- P4: chunk 0 (q) mma ----
    ZERO_ACC();
    MMA_CHUNK();
    __syncthreads();

    // ---- P5: stage chunk-1 weights || in-register softmax over d + direct q STG ----
    STAGE_W(1);
    {
        float* qg = g_qsoft + ((size_t)b * HID + wo * 32) * NPIX + i0 + wp * 32;
#pragma unroll
        for (int nt = 0; nt < 4; nt++) {
            // max over d (thread-local 4 values per px-lsb, then ty-lane reduce)
            float mx0 = fmaxf(fmaxf(acc[0][nt][0], acc[0][nt][2]), fmaxf(acc[1][nt][0], acc[1][nt][2]));
            float mx1 = fmaxf(fmaxf(acc[0][nt][1], acc[0][nt][3]), fmaxf(acc[1][nt][1], acc[1][nt][3]));
            mx0 = fmaxf(mx0, __shfl_xor_sync(0xFFFFFFFFu, mx0, 4));
            mx0 = fmaxf(mx0, __shfl_xor_sync(0xFFFFFFFFu, mx0, 8));
            mx0 = fmaxf(mx0, __shfl_xor_sync(0xFFFFFFFFu, mx0, 16));
            mx1 = fmaxf(mx1, __shfl_xor_sync(0xFFFFFFFFu, mx1, 4));
            mx1 = fmaxf(mx1, __shfl_xor_sync(0xFFFFFFFFu, mx1, 8));
            mx1 = fmaxf(mx1, __shfl_xor_sync(0xFFFFFFFFu, mx1, 16));
#pragma unroll
            for (int mt = 0; mt < 2; mt++) {
                acc[mt][nt][0] = __expf(acc[mt][nt][0] - mx0);
                acc[mt][nt][1] = __expf(acc[mt][nt][1] - mx1);
                acc[mt][nt][2] = __expf(acc[mt][nt][2] - mx0);
                acc[mt][nt][3] = __expf(acc[mt][nt][3] - mx1);
            }
            float s0 = acc[0][nt][0] + acc[0][nt][2] + acc[1][nt][0] + acc[1][nt][2];
            float s1 = acc[0][nt][1] + acc[0][nt][3] + acc[1][nt][1] + acc[1][nt][3];
            s0 += __shfl_xor_sync(0xFFFFFFFFu, s0, 4);
            s0 += __shfl_xor_sync(0xFFFFFFFFu, s0, 8);
            s0 += __shfl_xor_sync(0xFFFFFFFFu, s0, 16);
            s1 += __shfl_xor_sync(0xFFFFFFFFu, s1, 4);
            s1 += __shfl_xor_sync(0xFFFFFFFFu, s1, 8);
            s1 += __shfl_xor_sync(0xFFFFFFFFu, s1, 16);
            float rs0 = SCALE_Q / s0, rs1 = SCALE_Q / s1;
#pragma unroll
            for (int mt = 0; mt < 2; mt++)
#pragma unroll
                for (int hi = 0; hi < 2; hi++) {
                    int row = 16 * mt + ty + 8 * hi;
                    float2 v = make_float2(to_tf32(acc[mt][nt][2 * hi] * rs0),
                                           to_tf32(acc[mt][nt][2 * hi + 1] * rs1));
                    *(float2*)(qg + (size_t)row * NPIX + nt * 8 + 2 * tx) = v;
                }
        }
    }
    __syncthreads();

    // ---- P6: chunk 1 (k) mma ----
    ZERO_ACC();
    MMA_CHUNK();
    __syncthreads();

    // ---- P7: stage chunk-2 weights || exp(k) park + Z shuffle partials ----
    STAGE_W(2);
#pragma unroll
    for (int mt = 0; mt < 2; mt++) {
        float p0 = 0.f, p1 = 0.f;
        int r = wo * 32 + mt * 16 + ty;
#pragma unroll
        for (int nt = 0; nt < 4; nt++) {
            float e0 = __expf(acc[mt][nt][0]);
            float e1 = __expf(acc[mt][nt][1]);
            float e2 = __expf(acc[mt][nt][2]);
            float e3 = __expf(acc[mt][nt][3]);
            int c = wp * 32 + nt * 8 + 2 * tx;
            *(float2*)(sek + r * PQP + c)       = make_float2(to_tf32(e0), to_tf32(e1));
            *(float2*)(sek + (r + 8) * PQP + c) = make_float2(to_tf32(e2), to_tf32(e3));
            p0 += e0 + e1;
            p1 += e2 + e3;
        }
        p0 += __shfl_xor_sync(0xFFFFFFFF, p0, 1);
        p0 += __shfl_xor_sync(0xFFFFFFFF, p0, 2);
        p1 += __shfl_xor_sync(0xFFFFFFFF, p1, 1);
        p1 += __shfl_xor_sync(0xFFFFFFFF, p1, 2);
        if (tx == 0) {
            szp[wp * 128 + r]     = p0;
            szp[wp * 128 + r + 8] = p1;
        }
    }
    __syncthreads();

    // ---- P8: Z reduce+write || chunk 2 (v) mma ----
    if (tid < 128) {
        float z = szp[tid] + szp[128 + tid] + szp[256 + tid] + szp[384 + tid];
        g_Zpart[(size_t)(b * NT2 + tile) * HID + tid] = z;
    }
    ZERO_ACC();
    MMA_CHUNK();
    __syncthreads();

    // ---- P9: v park into sx (tf32) ----
#pragma unroll
    for (int mt = 0; mt < 2; mt++)
#pragma unroll
        for (int nt = 0; nt < 4; nt++) {
            int r = wo * 32 + mt * 16 + ty, c = wp * 32 + nt * 8 + 2 * tx;
            *(float2*)(sx + r * PXP + c)       = make_float2(to_tf32(acc[mt][nt][0]), to_tf32(acc[mt][nt][1]));
            *(float2*)(sx + (r + 8) * PXP + c) = make_float2(to_tf32(acc[mt][nt][2]), to_tf32(acc[mt][nt][3]));
        }
    __syncthreads();

    // ---- P10: context mma  S[h,d,e] = sum_px ek[h,d,px] * v[h,e,px] ----
    {
        int h = warp >> 2, dt = (warp >> 1) & 1, eh = warp & 1;
        float cacc[2][4];
#pragma unroll
        for (int et = 0; et < 2; et++) {
            cacc[et][0] = 0.f; cacc[et][1] = 0.f; cacc[et][2] = 0.f; cacc[et][3] = 0.f;
        }
#pragma unroll
        for (int ksc = 0; ksc < 16; ksc++) {
            int ii = ksc * 8;
            const float* ap = sek + (h * DH + dt * 16 + ty) * PQP + ii + tx;
            uint32_t a0 = __float_as_uint(ap[0]);
            uint32_t a1 = __float_as_uint(ap[8 * PQP]);
            uint32_t a2 = __float_as_uint(ap[4]);
            uint32_t a3 = __float_as_uint(ap[8 * PQP + 4]);
#pragma unroll
            for (int et = 0; et < 2; et++) {
                const float* bp = sx + (h * DH + eh * 16 + et * 8 + ty) * PXP + ii + tx;
                uint32_t b0 = __float_as_uint(bp[0]);
                uint32_t b1 = __float_as_uint(bp[4]);
                mma8(cacc[et], a0, a1, a2, a3, b0, b1);
            }
        }
        float* sp = g_Spart + ((size_t)(b * NT2 + tile)) * (HEADS * DH * DH) + h * DH * DH;
#pragma unroll
        for (int et = 0; et < 2; et++) {
            int d = dt * 16 + ty, e = eh * 16 + et * 8 + 2 * tx;
            *(float2*)(sp + d * DH + e)       = make_float2(cacc[et][0], cacc[et][1]);
            *(float2*)(sp + (d + 8) * DH + e) = make_float2(cacc[et][2], cacc[et][3]);
        }
    }
#undef ZERO_ACC
#undef MMA_CHUNK
#undef STAGE_W
}

// ================= K3: reduce partials per (b, head), fold context into w_out (frag-major) =================
__global__ void __launch_bounds__(256) k_ctx(const float* __restrict__ mem_kv,
                                             const float* __restrict__ w_out) {
    __shared__ float sctx[DH * DH];
    __shared__ float sZ[DH];
    int b = blockIdx.x, h = blockIdx.y, tid = threadIdx.x;

    if (tid < DH) {
        int d = tid;
        float z = 0.f;
#pragma unroll 4
        for (int t = 0; t < NT2; t++)
            z += g_Zpart[(size_t)(b * NT2 + t) * HID + h * DH + d];
        const float* mk = mem_kv + (h * DH + d) * 4;
        for (int j = 0; j < 4; j++) z += __expf(mk[j]);
        sZ[d] = z;
    }
    __syncthreads();

    for (int idx = tid; idx < DH * DH; idx += 256) {
        int d = idx >> 5, e = idx & 31;
        float s = 0.f;
#pragma unroll 4
        for (int t = 0; t < NT2; t++)
            s += g_Spart[(size_t)(b * NT2 + t) * (HEADS * DH * DH) + h * DH * DH + idx];
        const float* mk = mem_kv + (h * DH + d) * 4;
        const float* mv = mem_kv + (HEADS * DH + h * DH + e) * 4;
        for (int j = 0; j < 4; j++) s = fmaf(__expf(mk[j]), mv[j], s);
        sctx[idx] = s / sZ[d];
    }
    __syncthreads();

    // M[co][h*32+d] = sum_e w_out[co][h*32+e] * ctx[d][e]  -> frag-major g_Mperm
    for (int oidx = tid; oidx < HID * DH; oidx += 256) {
        int co = oidx >> 5, d = oidx & 31;
        const float* wrow = w_out + co * HID + h * DH;
        const float* crow = sctx + d * DH;
        float m = 0.f;
#pragma unroll
        for (int e = 0; e < DH; e++) m = fmaf(wrow[e], crow[e], m);
        int kd = h * DH + d;
        g_Mperm[b * 16384 + frag_pos(kd >> 3, co >> 4, co & 15, kd & 7)] = to_tf32(m);
    }
}

// ================= K4: output GEMM: out = Mperm @ qsoft + b_out  (2 blocks/SM) =================
#define K4_SMEM_FLOATS (CH*PXO + 16384)
#define K4_SMEM_BYTES  (K4_SMEM_FLOATS * 4)

__global__ void __launch_bounds__(256, 2) k_out(const float* __restrict__ bout,
                                                float* __restrict__ out) {
    extern __shared__ float sm[];
    float* sB = sm;               // [128 k][PXO] q tile; reused as output stage
    float* sA = sB + CH * PXO;    // [16384] frag-major M
    __shared__ float sb[HID];

    const int tid  = threadIdx.x;
    const int b    = blockIdx.y;
    const int tile = blockIdx.x;
    const int i0   = tile * TPO;
    const int warp = tid >> 5, lane = tid & 31;
    const int ty   = lane >> 2, tx = lane & 3;
    const int wo   = warp >> 1;        // 0..3 : o rows wo*32
    const int wp   = warp & 1;         // 0..1 : px wp*32

    if (tid < HID) sb[tid] = bout[tid];

    const float* qb = g_qsoft + (size_t)b * HID * NPIX;
#pragma unroll
    for (int t = 0; t < 8; t++) {
        int e = tid + t * 256;
        int p = e >> 4, i4 = (e & 15) << 2;
        float4 v = *(const float4*)(qb + (size_t)p * NPIX + i0 + i4);
        *(float4*)(sB + p * PXO + i4) = v;
    }
    const float* Mb = g_Mperm + (size_t)b * 16384;
#pragma unroll
    for (int t = 0; t < 16; t++) {
        int i4 = (tid + t * 256) << 2;
        *(float4*)(sA + i4) = *(const float4*)(Mb + i4);
    }
    __syncthreads();

    float acc[2][4][4];
#pragma unroll
    for (int mt = 0; mt < 2; mt++)
#pragma unroll
        for (int nt = 0; nt < 4; nt++) {
            acc[mt][nt][0] = 0.f; acc[mt][nt][1] = 0.f;
            acc[mt][nt][2] = 0.f; acc[mt][nt][3] = 0.f;
        }

#pragma unroll
    for (int ks = 0; ks < 16; ks++) {
        int kk = ks * 8;
        float4 af0 = *(const float4*)(sA + ((ks * 8 + 2 * wo + 0) * 32 + lane) * 4);
        float4 af1 = *(const float4*)(sA + ((ks * 8 + 2 * wo + 1) * 32 + lane) * 4);
        uint32_t bb[4][2];
#pragma unroll
        for (int nt = 0; nt < 4; nt++) {
            int px0 = wp * 32 + nt * 8 + ty;
            bb[nt][0] = __float_as_uint(sB[(kk + tx) * PXO + px0]);
            bb[nt][1] = __float_as_uint(sB[(kk + tx + 4) * PXO + px0]);
        }
#pragma unroll
        for (int nt = 0; nt < 4; nt++) {
            mma8(acc[0][nt], __float_as_uint(af0.x), __float_as_uint(af0.y),
                 __float_as_uint(af0.z), __float_as_uint(af0.w), bb[nt][0], bb[nt][1]);
            mma8(acc[1][nt], __float_as_uint(af1.x), __float_as_uint(af1.y),
                 __float_as_uint(af1.z), __float_as_uint(af1.w), bb[nt][0], bb[nt][1]);
        }
    }
    __syncthreads();
    // stage output (+bias), then coalesced float4 copy out
#pragma unroll
    for (int mt = 0; mt < 2; mt++)
#pragma unroll
        for (int nt = 0; nt < 4; nt++) {
            int r = wo * 32 + mt * 16 + ty, c = wp * 32 + nt * 8 + 2 * tx;
            *(float2*)(sB + r * PXO + c)       = make_float2(acc[mt][nt][0] + sb[r], acc[mt][nt][1] + sb[r]);
            *(float2*)(sB + (r + 8) * PXO + c) = make_float2(acc[mt][nt][2] + sb[r + 8], acc[mt][nt][3] + sb[r + 8]);
        }
    __syncthreads();
    float* ob = out + (size_t)b * HID * NPIX + i0;
#pragma unroll
    for (int t = 0; t < 8; t++) {
        int e = tid + t * 256;
        int o = e >> 4, i4 = (e & 15) << 2;
        float4 v = *(const float4*)(sB + o * PXO + i4);
        *(float4*)(ob + (size_t)o * NPIX + i4) = v;
    }
}

// ================= launch =================
extern "C" void kernel_launch(void* const* d_in, const int* in_sizes, int n_in,
                              void* d_out, int out_size) {
    const float* x     = (const float*)d_in[0];
    const float* g     = (const float*)d_in[1];
    const float* wqkv  = (const float*)d_in[2];
    const float* memkv = (const float*)d_in[3];
    const float* wout  = (const float*)d_in[4];
    const float* bout  = (const float*)d_in[5];
    float* out = (float*)d_out;

    cudaFuncSetAttribute(k_qkv, cudaFuncAttributeMaxDynamicSharedMemorySize, K2_SMEM_BYTES);
    cudaFuncSetAttribute(k_out, cudaFuncAttributeMaxDynamicSharedMemorySize, K4_SMEM_BYTES);

    k_prep<<<192, 256>>>(wqkv);
    k_qkv<<<dim3(NT2, BATCH), 512, K2_SMEM_BYTES>>>(x, g);
    k_ctx<<<dim3(BATCH, HEADS), 256>>>(memkv, wout);
    k_out<<<dim3(NTO, BATCH), 256, K4_SMEM_BYTES>>>(bout, out);
}